// round 1
// baseline (speedup 1.0000x reference)
#include <cuda_runtime.h>
#include <math.h>

#define B_ 4
#define S_ 2048
#define D_ 768
#define H_ 12
#define DH_ 64
#define M_TOT (B_ * S_)          // 8192
#define NELEM (M_TOT * D_)       // 6291456

// Scratch (device globals; allocation-free per harness rules)
__device__ float g_Q[NELEM];
__device__ float g_K[NELEM];
__device__ float g_V[NELEM];
__device__ float g_C[NELEM];

// ---------------------------------------------------------------------------
// GEMM: Y[M,N] = X[M,K] @ W[N,K]^T + bias[N]
// 64x64 block tile, BK=16, 256 threads, 4x4 per-thread micro-tile.
// ---------------------------------------------------------------------------
__global__ __launch_bounds__(256) void gemm_xwt_bias(
    const float* __restrict__ X, const float* __restrict__ W,
    const float* __restrict__ bias, float* __restrict__ Y,
    int M, int N, int K)
{
    __shared__ float Xs[16][68];   // [k][m], padded stride 68
    __shared__ float Ws[16][68];   // [k][n]

    const int tid = threadIdx.x;
    const int tx = tid & 15;       // 0..15 -> n micro
    const int ty = tid >> 4;       // 0..15 -> m micro
    const int m0 = blockIdx.y * 64;
    const int n0 = blockIdx.x * 64;
    const int lr = tid >> 2;       // 0..63 loader row
    const int lq = tid & 3;        // 0..3  loader float4 slot

    const float* xrow = X + (size_t)(m0 + lr) * K + 4 * lq;
    const float* wrow = W + (size_t)(n0 + lr) * K + 4 * lq;

    float acc[4][4] = {};

    for (int k0 = 0; k0 < K; k0 += 16) {
        float4 xv = *(const float4*)(xrow + k0);
        float4 wv = *(const float4*)(wrow + k0);
        __syncthreads();
        Xs[4 * lq + 0][lr] = xv.x;
        Xs[4 * lq + 1][lr] = xv.y;
        Xs[4 * lq + 2][lr] = xv.z;
        Xs[4 * lq + 3][lr] = xv.w;
        Ws[4 * lq + 0][lr] = wv.x;
        Ws[4 * lq + 1][lr] = wv.y;
        Ws[4 * lq + 2][lr] = wv.z;
        Ws[4 * lq + 3][lr] = wv.w;
        __syncthreads();

#pragma unroll
        for (int d = 0; d < 16; d++) {
            float4 a = *(const float4*)&Xs[d][ty * 4];
            float4 b = *(const float4*)&Ws[d][tx * 4];
            acc[0][0] += a.x * b.x; acc[0][1] += a.x * b.y; acc[0][2] += a.x * b.z; acc[0][3] += a.x * b.w;
            acc[1][0] += a.y * b.x; acc[1][1] += a.y * b.y; acc[1][2] += a.y * b.z; acc[1][3] += a.y * b.w;
            acc[2][0] += a.z * b.x; acc[2][1] += a.z * b.y; acc[2][2] += a.z * b.z; acc[2][3] += a.z * b.w;
            acc[3][0] += a.w * b.x; acc[3][1] += a.w * b.y; acc[3][2] += a.w * b.z; acc[3][3] += a.w * b.w;
        }
    }

    float b0 = bias[n0 + tx * 4 + 0];
    float b1 = bias[n0 + tx * 4 + 1];
    float b2 = bias[n0 + tx * 4 + 2];
    float b3 = bias[n0 + tx * 4 + 3];
#pragma unroll
    for (int i = 0; i < 4; i++) {
        float4 o;
        o.x = acc[i][0] + b0;
        o.y = acc[i][1] + b1;
        o.z = acc[i][2] + b2;
        o.w = acc[i][3] + b3;
        *(float4*)&Y[(size_t)(m0 + ty * 4 + i) * N + n0 + tx * 4] = o;
    }
}

// ---------------------------------------------------------------------------
// Fused attention: per (b, h, 64-row q tile), stream 64-wide K/V tiles.
// attn = mix0 * softmax(S) + mix1 * relu(S)^2 ;  S = QK^T / 8
// Scores are small (|S| ~ <2) so exp() needs no max subtraction; keep
// unnormalized running sums and normalize the softmax branch at the end.
// ---------------------------------------------------------------------------
#define TPITCH 68
#define TSZ (64 * TPITCH)

__global__ __launch_bounds__(256) void attn_kernel(
    const float* __restrict__ Q, const float* __restrict__ K,
    const float* __restrict__ V, const float* __restrict__ wmix,
    float* __restrict__ C)
{
    extern __shared__ float sm[];
    float* Qs = sm;                 // [d][r]
    float* Ks = sm + TSZ;           // [d][c]
    float* Vs = sm + 2 * TSZ;       // [c][dh]
    float* Ps = sm + 3 * TSZ;       // exp(S) [r][c]
    float* Pr = sm + 4 * TSZ;       // relu(S)^2 [r][c]

    const int tid = threadIdx.x;
    const int tx = tid & 15;
    const int ty = tid >> 4;
    const int qt = blockIdx.x;      // 0..31
    const int h = blockIdx.y;       // 0..11
    const int b = blockIdx.z;       // 0..3
    const int s0 = qt * 64;
    const size_t base = (size_t)b * S_ * D_ + (size_t)h * DH_;
    const int lr = tid >> 2;
    const int lq = tid & 3;

    // Load Q tile transposed: Qs[d][r]
    {
        const float* q = Q + base + (size_t)(s0 + lr) * D_;
#pragma unroll
        for (int u = 0; u < 4; u++) {
            int d0 = 4 * lq + 16 * u;
            float4 v = *(const float4*)(q + d0);
            Qs[(d0 + 0) * TPITCH + lr] = v.x;
            Qs[(d0 + 1) * TPITCH + lr] = v.y;
            Qs[(d0 + 2) * TPITCH + lr] = v.z;
            Qs[(d0 + 3) * TPITCH + lr] = v.w;
        }
    }

    float os[4][4] = {};
    float orl[4][4] = {};
    float lsum[4] = {};

    for (int kt = 0; kt < 32; kt++) {
        __syncthreads();  // previous AV pass done: Ks/Vs/Ps writable
        {
            const float* kp = K + base + (size_t)(kt * 64 + lr) * D_;
            const float* vp = V + base + (size_t)(kt * 64 + lr) * D_;
#pragma unroll
            for (int u = 0; u < 4; u++) {
                int d0 = 4 * lq + 16 * u;
                float4 kv = *(const float4*)(kp + d0);
                Ks[(d0 + 0) * TPITCH + lr] = kv.x;
                Ks[(d0 + 1) * TPITCH + lr] = kv.y;
                Ks[(d0 + 2) * TPITCH + lr] = kv.z;
                Ks[(d0 + 3) * TPITCH + lr] = kv.w;
                float4 vv = *(const float4*)(vp + d0);
                *(float4*)&Vs[lr * TPITCH + d0] = vv;
            }
        }
        __syncthreads();

        // Scores: s[4][4] = Q_tile @ K_tile^T
        float s[4][4] = {};
#pragma unroll 8
        for (int d = 0; d < 64; d++) {
            float4 a = *(const float4*)&Qs[d * TPITCH + ty * 4];
            float4 bb = *(const float4*)&Ks[d * TPITCH + tx * 4];
            s[0][0] += a.x * bb.x; s[0][1] += a.x * bb.y; s[0][2] += a.x * bb.z; s[0][3] += a.x * bb.w;
            s[1][0] += a.y * bb.x; s[1][1] += a.y * bb.y; s[1][2] += a.y * bb.z; s[1][3] += a.y * bb.w;
            s[2][0] += a.z * bb.x; s[2][1] += a.z * bb.y; s[2][2] += a.z * bb.z; s[2][3] += a.z * bb.w;
            s[3][0] += a.w * bb.x; s[3][1] += a.w * bb.y; s[3][2] += a.w * bb.z; s[3][3] += a.w * bb.w;
        }

        // Elementwise: exp + relu^2, write both P tiles
#pragma unroll
        for (int i = 0; i < 4; i++) {
            float4 pe, pq;
            float sc;
            sc = s[i][0] * 0.125f; pe.x = __expf(sc); pq.x = sc > 0.f ? sc * sc : 0.f;
            sc = s[i][1] * 0.125f; pe.y = __expf(sc); pq.y = sc > 0.f ? sc * sc : 0.f;
            sc = s[i][2] * 0.125f; pe.z = __expf(sc); pq.z = sc > 0.f ? sc * sc : 0.f;
            sc = s[i][3] * 0.125f; pe.w = __expf(sc); pq.w = sc > 0.f ? sc * sc : 0.f;
            lsum[i] += pe.x + pe.y + pe.z + pe.w;
            *(float4*)&Ps[(ty * 4 + i) * TPITCH + tx * 4] = pe;
            *(float4*)&Pr[(ty * 4 + i) * TPITCH + tx * 4] = pq;
        }
        __syncthreads();

        // AV: os += Ps @ V, orl += Pr @ V  (shared V read)
#pragma unroll 8
        for (int c = 0; c < 64; c++) {
            float4 v = *(const float4*)&Vs[c * TPITCH + tx * 4];
            float as0 = Ps[(ty * 4 + 0) * TPITCH + c];
            float as1 = Ps[(ty * 4 + 1) * TPITCH + c];
            float as2 = Ps[(ty * 4 + 2) * TPITCH + c];
            float as3 = Ps[(ty * 4 + 3) * TPITCH + c];
            float ar0 = Pr[(ty * 4 + 0) * TPITCH + c];
            float ar1 = Pr[(ty * 4 + 1) * TPITCH + c];
            float ar2 = Pr[(ty * 4 + 2) * TPITCH + c];
            float ar3 = Pr[(ty * 4 + 3) * TPITCH + c];
            os[0][0] += as0 * v.x; os[0][1] += as0 * v.y; os[0][2] += as0 * v.z; os[0][3] += as0 * v.w;
            os[1][0] += as1 * v.x; os[1][1] += as1 * v.y; os[1][2] += as1 * v.z; os[1][3] += as1 * v.w;
            os[2][0] += as2 * v.x; os[2][1] += as2 * v.y; os[2][2] += as2 * v.z; os[2][3] += as2 * v.w;
            os[3][0] += as3 * v.x; os[3][1] += as3 * v.y; os[3][2] += as3 * v.z; os[3][3] += as3 * v.w;
            orl[0][0] += ar0 * v.x; orl[0][1] += ar0 * v.y; orl[0][2] += ar0 * v.z; orl[0][3] += ar0 * v.w;
            orl[1][0] += ar1 * v.x; orl[1][1] += ar1 * v.y; orl[1][2] += ar1 * v.z; orl[1][3] += ar1 * v.w;
            orl[2][0] += ar2 * v.x; orl[2][1] += ar2 * v.y; orl[2][2] += ar2 * v.z; orl[2][3] += ar2 * v.w;
            orl[3][0] += ar3 * v.x; orl[3][1] += ar3 * v.y; orl[3][2] += ar3 * v.z; orl[3][3] += ar3 * v.w;
        }
    }

    // Row-sum reduction for l across the 16 lanes sharing each q-row
#pragma unroll
    for (int i = 0; i < 4; i++) {
        float v = lsum[i];
        v += __shfl_xor_sync(0xffffffffu, v, 1, 16);
        v += __shfl_xor_sync(0xffffffffu, v, 2, 16);
        v += __shfl_xor_sync(0xffffffffu, v, 4, 16);
        v += __shfl_xor_sync(0xffffffffu, v, 8, 16);
        lsum[i] = v;
    }

    // Mix weights: softmax(w_mix)
    float e0 = __expf(wmix[0]);
    float e1 = __expf(wmix[1]);
    float inv = 1.0f / (e0 + e1);
    float m0 = e0 * inv, m1 = e1 * inv;

#pragma unroll
    for (int i = 0; i < 4; i++) {
        float fs = m0 / lsum[i];
        float4 o;
        o.x = os[i][0] * fs + m1 * orl[i][0];
        o.y = os[i][1] * fs + m1 * orl[i][1];
        o.z = os[i][2] * fs + m1 * orl[i][2];
        o.w = os[i][3] * fs + m1 * orl[i][3];
        *(float4*)&C[base + (size_t)(s0 + ty * 4 + i) * D_ + tx * 4] = o;
    }
}

// ---------------------------------------------------------------------------
extern "C" void kernel_launch(void* const* d_in, const int* in_sizes, int n_in,
                              void* d_out, int out_size)
{
    const float* hs   = (const float*)d_in[0];
    const float* Wq   = (const float*)d_in[1];
    const float* bq   = (const float*)d_in[2];
    const float* Wk   = (const float*)d_in[3];
    const float* bk   = (const float*)d_in[4];
    const float* Wv   = (const float*)d_in[5];
    const float* bv   = (const float*)d_in[6];
    const float* Wo   = (const float*)d_in[7];
    const float* bo   = (const float*)d_in[8];
    const float* wmix = (const float*)d_in[9];
    float* out = (float*)d_out;

    float *q, *k, *v, *c;
    cudaGetSymbolAddress((void**)&q, g_Q);
    cudaGetSymbolAddress((void**)&k, g_K);
    cudaGetSymbolAddress((void**)&v, g_V);
    cudaGetSymbolAddress((void**)&c, g_C);

    dim3 gg(D_ / 64, M_TOT / 64);   // (12, 128)
    gemm_xwt_bias<<<gg, 256>>>(hs, Wq, bq, q, M_TOT, D_, D_);
    gemm_xwt_bias<<<gg, 256>>>(hs, Wk, bk, k, M_TOT, D_, D_);
    gemm_xwt_bias<<<gg, 256>>>(hs, Wv, bv, v, M_TOT, D_, D_);

    size_t smem = 5 * TSZ * sizeof(float);   // 87040 bytes
    cudaFuncSetAttribute(attn_kernel, cudaFuncAttributeMaxDynamicSharedMemorySize, (int)smem);
    attn_kernel<<<dim3(S_ / 64, H_, B_), 256, smem>>>(q, k, v, wmix, c);

    gemm_xwt_bias<<<gg, 256>>>(c, Wo, bo, out, M_TOT, D_, D_);
}

// round 2
// speedup vs baseline: 2.4500x; 2.4500x over previous
#include <cuda_runtime.h>
#include <math.h>

#define B_ 4
#define S_ 2048
#define D_ 768
#define H_ 12
#define DH_ 64
#define M_TOT (B_ * S_)          // 8192
#define NELEM (M_TOT * D_)       // 6291456

__device__ float g_Q[NELEM];
__device__ float g_K[NELEM];
__device__ float g_V[NELEM];
__device__ float g_C[NELEM];

__device__ __forceinline__ float tf32r(float f) {
    unsigned u;
    asm("cvt.rna.tf32.f32 %0, %1;" : "=r"(u) : "f"(f));
    return __uint_as_float(u);
}

__device__ __forceinline__ void mma8(float* c, float a0, float a1, float a2, float a3,
                                     float b0, float b1) {
    asm volatile(
        "mma.sync.aligned.m16n8k8.row.col.f32.tf32.tf32.f32 "
        "{%0,%1,%2,%3},{%4,%5,%6,%7},{%8,%9},{%0,%1,%2,%3};\n"
        : "+f"(c[0]), "+f"(c[1]), "+f"(c[2]), "+f"(c[3])
        : "r"(__float_as_uint(a0)), "r"(__float_as_uint(a1)),
          "r"(__float_as_uint(a2)), "r"(__float_as_uint(a3)),
          "r"(__float_as_uint(b0)), "r"(__float_as_uint(b1)));
}

// ---------------------------------------------------------------------------
// GEMM: Y[M,N] = X[M,K] @ W[N,K]^T + bias[N]   (tf32 mma, 128x128x32 tiles)
// smem k-layout paired: position kk = (k&~7) | ((k&3)<<1) | ((k>>2)&1)
// so A frag (a0,a2)=(k=tig, k=tig+4) is one float2; B frag (b0,b1) likewise.
// ---------------------------------------------------------------------------
#define GP 40

__global__ __launch_bounds__(256) void gemm_tf32(
    const float* __restrict__ X, const float* __restrict__ W,
    const float* __restrict__ bias, float* __restrict__ Y,
    int M, int N, int K)
{
    __shared__ float Xs[128 * GP];
    __shared__ float Ws[128 * GP];

    const int tid = threadIdx.x;
    const int lane = tid & 31, wid = tid >> 5;
    const int g = lane >> 2, tig = lane & 3;
    const int wy = wid >> 2, wx = wid & 3;     // 2 x 4 warp grid
    const int m0 = blockIdx.y * 128, n0 = blockIdx.x * 128;

    const int lrow = tid >> 1;
    const int lk = (tid & 1) * 16;
    const float* xp = X + (size_t)(m0 + lrow) * K + lk;
    const float* wp = W + (size_t)(n0 + lrow) * K + lk;
    float* xs = &Xs[lrow * GP + lk];
    float* ws = &Ws[lrow * GP + lk];

    float acc[4][4][4] = {};

    for (int kb = 0; kb < K; kb += 32) {
        float4 x0 = *(const float4*)(xp + kb);
        float4 x1 = *(const float4*)(xp + kb + 4);
        float4 x2 = *(const float4*)(xp + kb + 8);
        float4 x3 = *(const float4*)(xp + kb + 12);
        float4 w0 = *(const float4*)(wp + kb);
        float4 w1 = *(const float4*)(wp + kb + 4);
        float4 w2 = *(const float4*)(wp + kb + 8);
        float4 w3 = *(const float4*)(wp + kb + 12);
        __syncthreads();
        {
            float4 o;
            o.x = tf32r(x0.x); o.y = tf32r(x1.x); o.z = tf32r(x0.y); o.w = tf32r(x1.y);
            *(float4*)(xs + 0) = o;
            o.x = tf32r(x0.z); o.y = tf32r(x1.z); o.z = tf32r(x0.w); o.w = tf32r(x1.w);
            *(float4*)(xs + 4) = o;
            o.x = tf32r(x2.x); o.y = tf32r(x3.x); o.z = tf32r(x2.y); o.w = tf32r(x3.y);
            *(float4*)(xs + 8) = o;
            o.x = tf32r(x2.z); o.y = tf32r(x3.z); o.z = tf32r(x2.w); o.w = tf32r(x3.w);
            *(float4*)(xs + 12) = o;
            o.x = tf32r(w0.x); o.y = tf32r(w1.x); o.z = tf32r(w0.y); o.w = tf32r(w1.y);
            *(float4*)(ws + 0) = o;
            o.x = tf32r(w0.z); o.y = tf32r(w1.z); o.z = tf32r(w0.w); o.w = tf32r(w1.w);
            *(float4*)(ws + 4) = o;
            o.x = tf32r(w2.x); o.y = tf32r(w3.x); o.z = tf32r(w2.y); o.w = tf32r(w3.y);
            *(float4*)(ws + 8) = o;
            o.x = tf32r(w2.z); o.y = tf32r(w3.z); o.z = tf32r(w2.w); o.w = tf32r(w3.w);
            *(float4*)(ws + 12) = o;
        }
        __syncthreads();

#pragma unroll
        for (int ks = 0; ks < 4; ks++) {
            float2 al[4], ah[4], bf[4];
#pragma unroll
            for (int mt = 0; mt < 4; mt++) {
                int r = wy * 64 + mt * 16 + g;
                al[mt] = *(float2*)&Xs[r * GP + ks * 8 + 2 * tig];
                ah[mt] = *(float2*)&Xs[(r + 8) * GP + ks * 8 + 2 * tig];
            }
#pragma unroll
            for (int nt = 0; nt < 4; nt++)
                bf[nt] = *(float2*)&Ws[(wx * 32 + nt * 8 + g) * GP + ks * 8 + 2 * tig];
#pragma unroll
            for (int mt = 0; mt < 4; mt++)
#pragma unroll
                for (int nt = 0; nt < 4; nt++)
                    mma8(acc[mt][nt], al[mt].x, ah[mt].x, al[mt].y, ah[mt].y,
                         bf[nt].x, bf[nt].y);
        }
    }

#pragma unroll
    for (int nt = 0; nt < 4; nt++) {
        int c = n0 + wx * 32 + nt * 8 + 2 * tig;
        float b0v = bias[c], b1v = bias[c + 1];
#pragma unroll
        for (int mt = 0; mt < 4; mt++) {
            int r = m0 + wy * 64 + mt * 16 + g;
            float2 o0 = {acc[mt][nt][0] + b0v, acc[mt][nt][1] + b1v};
            float2 o1 = {acc[mt][nt][2] + b0v, acc[mt][nt][3] + b1v};
            *(float2*)&Y[(size_t)r * N + c] = o0;
            *(float2*)&Y[(size_t)(r + 8) * N + c] = o1;
        }
    }
}

// ---------------------------------------------------------------------------
// Attention: per block (128 q rows, head h, batch b); stream 64-wide kv tiles.
// S = QK^T/8 via mma; P_soft=exp(S), P_relu=relu(S)^2 -> smem; ctx += P@V via mma.
// Qs/Ks pitch 72 (conflict-free float2 frag loads); Vs/Ps/Pr pitch 68
// (conflict-free scalar frag loads).
// ---------------------------------------------------------------------------
#define AP1 72
#define AP2 68
#define OFF_Q 0
#define OFF_K (128 * AP1)                 // 9216
#define OFF_V (OFF_K + 64 * AP1)          // 13824
#define OFF_PS (OFF_V + 64 * AP2)         // 18176
#define OFF_PR (OFF_PS + 128 * AP2)       // 26880
#define OFF_L (OFF_PR + 128 * AP2)        // 35584
#define SM_FLOATS (OFF_L + 256)           // 35840

__global__ __launch_bounds__(256) void attn_tf32(
    const float* __restrict__ Q, const float* __restrict__ K,
    const float* __restrict__ V, const float* __restrict__ wmix,
    float* __restrict__ C)
{
    extern __shared__ float sm[];
    float* Qs = sm + OFF_Q;
    float* Ks = sm + OFF_K;
    float* Vs = sm + OFF_V;
    float* Ps = sm + OFF_PS;
    float* Pr = sm + OFF_PR;
    float* Ls = sm + OFF_L;

    const int tid = threadIdx.x;
    const int lane = tid & 31, wid = tid >> 5;
    const int g = lane >> 2, tig = lane & 3;
    const int wy = wid >> 1, wx = wid & 1;     // 4m x 2n warp grid
    const int s0 = blockIdx.x * 128;
    const int h = blockIdx.y;
    const int b = blockIdx.z;
    const size_t base = (size_t)b * S_ * D_ + (size_t)h * DH_;

    // Q tile (128 x 64), tf32, k-paired, pitch 72
    {
        int row = tid >> 1, cb = (tid & 1) * 32;
        const float* qp = Q + base + (size_t)(s0 + row) * D_ + cb;
        float* qs = &Qs[row * AP1 + cb];
#pragma unroll
        for (int gb = 0; gb < 4; gb++) {
            float4 v0 = *(const float4*)(qp + gb * 8);
            float4 v1 = *(const float4*)(qp + gb * 8 + 4);
            float4 o0, o1;
            o0.x = tf32r(v0.x); o0.y = tf32r(v1.x); o0.z = tf32r(v0.y); o0.w = tf32r(v1.y);
            o1.x = tf32r(v0.z); o1.y = tf32r(v1.z); o1.z = tf32r(v0.w); o1.w = tf32r(v1.w);
            *(float4*)(qs + gb * 8) = o0;
            *(float4*)(qs + gb * 8 + 4) = o1;
        }
    }

    float os[2][4][4] = {};
    float orl[2][4][4] = {};
    float lsum[4] = {0.f, 0.f, 0.f, 0.f};

    for (int kt = 0; kt < 32; kt++) {
        __syncthreads();
        // K tile (64 kv x 64 dh), k-paired, pitch 72
        {
            int row = tid >> 2, cb = (tid & 3) * 16;
            const float* kp = K + base + (size_t)(kt * 64 + row) * D_ + cb;
            float* ks_ = &Ks[row * AP1 + cb];
#pragma unroll
            for (int gb = 0; gb < 2; gb++) {
                float4 v0 = *(const float4*)(kp + gb * 8);
                float4 v1 = *(const float4*)(kp + gb * 8 + 4);
                float4 o0, o1;
                o0.x = tf32r(v0.x); o0.y = tf32r(v1.x); o0.z = tf32r(v0.y); o0.w = tf32r(v1.y);
                o1.x = tf32r(v0.z); o1.y = tf32r(v1.z); o1.z = tf32r(v0.w); o1.w = tf32r(v1.w);
                *(float4*)(ks_ + gb * 8) = o0;
                *(float4*)(ks_ + gb * 8 + 4) = o1;
            }
        }
        // V tile transposed: Vs[dh][kv], natural kv, pitch 68
        {
            int kv = tid & 63, dhb = (tid >> 6) * 16;
            const float* vp = V + base + (size_t)(kt * 64 + kv) * D_ + dhb;
#pragma unroll
            for (int j4 = 0; j4 < 4; j4++) {
                float4 v = *(const float4*)(vp + j4 * 4);
                Vs[(dhb + j4 * 4 + 0) * AP2 + kv] = tf32r(v.x);
                Vs[(dhb + j4 * 4 + 1) * AP2 + kv] = tf32r(v.y);
                Vs[(dhb + j4 * 4 + 2) * AP2 + kv] = tf32r(v.z);
                Vs[(dhb + j4 * 4 + 3) * AP2 + kv] = tf32r(v.w);
            }
        }
        __syncthreads();

        // S = Q @ K^T
        float sc[2][4][4] = {};
#pragma unroll
        for (int ks = 0; ks < 8; ks++) {
            float2 al[2], ah[2], bf[4];
#pragma unroll
            for (int mt = 0; mt < 2; mt++) {
                int r = wy * 32 + mt * 16 + g;
                al[mt] = *(float2*)&Qs[r * AP1 + ks * 8 + 2 * tig];
                ah[mt] = *(float2*)&Qs[(r + 8) * AP1 + ks * 8 + 2 * tig];
            }
#pragma unroll
            for (int nt = 0; nt < 4; nt++)
                bf[nt] = *(float2*)&Ks[(wx * 32 + nt * 8 + g) * AP1 + ks * 8 + 2 * tig];
#pragma unroll
            for (int mt = 0; mt < 2; mt++)
#pragma unroll
                for (int nt = 0; nt < 4; nt++)
                    mma8(sc[mt][nt], al[mt].x, ah[mt].x, al[mt].y, ah[mt].y,
                         bf[nt].x, bf[nt].y);
        }

        // exp / relu^2, write P tiles (pitch 68)
#pragma unroll
        for (int mt = 0; mt < 2; mt++) {
            int r0 = wy * 32 + mt * 16 + g;
#pragma unroll
            for (int nt = 0; nt < 4; nt++) {
                int cj = wx * 32 + nt * 8 + 2 * tig;
                float s0v = sc[mt][nt][0] * 0.125f;
                float s1v = sc[mt][nt][1] * 0.125f;
                float s2v = sc[mt][nt][2] * 0.125f;
                float s3v = sc[mt][nt][3] * 0.125f;
                float e0 = __expf(s0v), e1 = __expf(s1v);
                float e2 = __expf(s2v), e3 = __expf(s3v);
                lsum[mt * 2 + 0] += e0 + e1;
                lsum[mt * 2 + 1] += e2 + e3;
                float q0 = s0v > 0.f ? s0v * s0v : 0.f;
                float q1 = s1v > 0.f ? s1v * s1v : 0.f;
                float q2 = s2v > 0.f ? s2v * s2v : 0.f;
                float q3 = s3v > 0.f ? s3v * s3v : 0.f;
                float2 pe0 = {tf32r(e0), tf32r(e1)};
                float2 pe1 = {tf32r(e2), tf32r(e3)};
                float2 pq0 = {tf32r(q0), tf32r(q1)};
                float2 pq1 = {tf32r(q2), tf32r(q3)};
                *(float2*)&Ps[r0 * AP2 + cj] = pe0;
                *(float2*)&Ps[(r0 + 8) * AP2 + cj] = pe1;
                *(float2*)&Pr[r0 * AP2 + cj] = pq0;
                *(float2*)&Pr[(r0 + 8) * AP2 + cj] = pq1;
            }
        }
        __syncthreads();

        // ctx += P @ V (both P matrices share V B-fragments)
#pragma unroll
        for (int ks = 0; ks < 8; ks++) {
            float bp0[4], bp1[4];
#pragma unroll
            for (int nt = 0; nt < 4; nt++) {
                int r = wx * 32 + nt * 8 + g;
                bp0[nt] = Vs[r * AP2 + ks * 8 + tig];
                bp1[nt] = Vs[r * AP2 + ks * 8 + tig + 4];
            }
#pragma unroll
            for (int mt = 0; mt < 2; mt++) {
                int r = wy * 32 + mt * 16 + g;
                float a0 = Ps[r * AP2 + ks * 8 + tig];
                float a1 = Ps[(r + 8) * AP2 + ks * 8 + tig];
                float a2 = Ps[r * AP2 + ks * 8 + tig + 4];
                float a3 = Ps[(r + 8) * AP2 + ks * 8 + tig + 4];
                float c0 = Pr[r * AP2 + ks * 8 + tig];
                float c1 = Pr[(r + 8) * AP2 + ks * 8 + tig];
                float c2 = Pr[r * AP2 + ks * 8 + tig + 4];
                float c3 = Pr[(r + 8) * AP2 + ks * 8 + tig + 4];
#pragma unroll
                for (int nt = 0; nt < 4; nt++) {
                    mma8(os[mt][nt], a0, a1, a2, a3, bp0[nt], bp1[nt]);
                    mma8(orl[mt][nt], c0, c1, c2, c3, bp0[nt], bp1[nt]);
                }
            }
        }
    }

    // reduce lsum across the quad (lanes sharing a row)
#pragma unroll
    for (int i = 0; i < 4; i++) {
        float v = lsum[i];
        v += __shfl_xor_sync(0xffffffffu, v, 1);
        v += __shfl_xor_sync(0xffffffffu, v, 2);
        lsum[i] = v;
    }
    __syncthreads();
#pragma unroll
    for (int mt = 0; mt < 2; mt++) {
        int r0 = wy * 32 + mt * 16 + g;
        Ls[wx * 128 + r0] = lsum[mt * 2];
        Ls[wx * 128 + r0 + 8] = lsum[mt * 2 + 1];
    }
    __syncthreads();

    float e0 = __expf(wmix[0]), e1 = __expf(wmix[1]);
    float inv = 1.0f / (e0 + e1);
    float mix0 = e0 * inv, mix1 = e1 * inv;

#pragma unroll
    for (int mt = 0; mt < 2; mt++) {
        int r0 = wy * 32 + mt * 16 + g;
        float l0 = Ls[r0] + Ls[128 + r0];
        float l1 = Ls[r0 + 8] + Ls[128 + r0 + 8];
        float f0 = mix0 / l0, f1 = mix0 / l1;
#pragma unroll
        for (int nt = 0; nt < 4; nt++) {
            int cj = wx * 32 + nt * 8 + 2 * tig;
            float2 o0 = {os[mt][nt][0] * f0 + mix1 * orl[mt][nt][0],
                         os[mt][nt][1] * f0 + mix1 * orl[mt][nt][1]};
            float2 o1 = {os[mt][nt][2] * f1 + mix1 * orl[mt][nt][2],
                         os[mt][nt][3] * f1 + mix1 * orl[mt][nt][3]};
            *(float2*)&C[base + (size_t)(s0 + r0) * D_ + cj] = o0;
            *(float2*)&C[base + (size_t)(s0 + r0 + 8) * D_ + cj] = o1;
        }
    }
}

// ---------------------------------------------------------------------------
extern "C" void kernel_launch(void* const* d_in, const int* in_sizes, int n_in,
                              void* d_out, int out_size)
{
    const float* hs   = (const float*)d_in[0];
    const float* Wq   = (const float*)d_in[1];
    const float* bq   = (const float*)d_in[2];
    const float* Wk   = (const float*)d_in[3];
    const float* bk   = (const float*)d_in[4];
    const float* Wv   = (const float*)d_in[5];
    const float* bv   = (const float*)d_in[6];
    const float* Wo   = (const float*)d_in[7];
    const float* bo   = (const float*)d_in[8];
    const float* wmix = (const float*)d_in[9];
    float* out = (float*)d_out;

    float *q, *k, *v, *c;
    cudaGetSymbolAddress((void**)&q, g_Q);
    cudaGetSymbolAddress((void**)&k, g_K);
    cudaGetSymbolAddress((void**)&v, g_V);
    cudaGetSymbolAddress((void**)&c, g_C);

    dim3 gg(D_ / 128, M_TOT / 128);   // (6, 64)
    gemm_tf32<<<gg, 256>>>(hs, Wq, bq, q, M_TOT, D_, D_);
    gemm_tf32<<<gg, 256>>>(hs, Wk, bk, k, M_TOT, D_, D_);
    gemm_tf32<<<gg, 256>>>(hs, Wv, bv, v, M_TOT, D_, D_);

    size_t smem = SM_FLOATS * sizeof(float);   // 143360 bytes
    cudaFuncSetAttribute(attn_tf32, cudaFuncAttributeMaxDynamicSharedMemorySize, (int)smem);
    attn_tf32<<<dim3(S_ / 128, H_, B_), 256, smem>>>(q, k, v, wmix, c);

    gemm_tf32<<<gg, 256>>>(c, Wo, bo, out, M_TOT, D_, D_);
}

// round 3
// speedup vs baseline: 3.2378x; 1.3216x over previous
#include <cuda_runtime.h>
#include <math.h>

#define B_ 4
#define S_ 2048
#define D_ 768
#define H_ 12
#define DH_ 64
#define M_TOT (B_ * S_)          // 8192
#define NELEM (M_TOT * D_)       // 6291456

__device__ float g_Q[NELEM];
__device__ float g_K[NELEM];
__device__ float g_V[NELEM];
__device__ float g_C[NELEM];

__device__ __forceinline__ float tf32r(float f) {
    unsigned u;
    asm("cvt.rna.tf32.f32 %0, %1;" : "=r"(u) : "f"(f));
    return __uint_as_float(u);
}

__device__ __forceinline__ void mma8(float* c, float a0, float a1, float a2, float a3,
                                     float b0, float b1) {
    asm volatile(
        "mma.sync.aligned.m16n8k8.row.col.f32.tf32.tf32.f32 "
        "{%0,%1,%2,%3},{%4,%5,%6,%7},{%8,%9},{%0,%1,%2,%3};\n"
        : "+f"(c[0]), "+f"(c[1]), "+f"(c[2]), "+f"(c[3])
        : "r"(__float_as_uint(a0)), "r"(__float_as_uint(a1)),
          "r"(__float_as_uint(a2)), "r"(__float_as_uint(a3)),
          "r"(__float_as_uint(b0)), "r"(__float_as_uint(b1)));
}

__device__ __forceinline__ void cp16(unsigned dst, const void* src) {
    asm volatile("cp.async.cg.shared.global [%0], [%1], 16;" :: "r"(dst), "l"(src));
}
#define CP_COMMIT() asm volatile("cp.async.commit_group;")
#define CP_WAIT(N) asm volatile("cp.async.wait_group %0;" :: "n"(N))

// ---------------------------------------------------------------------------
// GEMM: Y[M,N] = X[M,K] @ W[N,K]^T + bias[N]   (tf32 mma, 128x128x32 tiles)
// MODE 0: plain f32 out; 1: tf32-rounded out; 2: (out*0.125) tf32-rounded.
// Register-staged prefetch: next k-slab LDG issues before current MMAs.
// ---------------------------------------------------------------------------
#define GP 40

template<int MODE>
__global__ __launch_bounds__(256, 2) void gemm_tf32(
    const float* __restrict__ X, const float* __restrict__ W,
    const float* __restrict__ bias, float* __restrict__ Y,
    int M, int N, int K)
{
    __shared__ float Xs[128 * GP];
    __shared__ float Ws[128 * GP];

    const int tid = threadIdx.x;
    const int lane = tid & 31, wid = tid >> 5;
    const int g = lane >> 2, tig = lane & 3;
    const int wy = wid >> 2, wx = wid & 3;     // 2 x 4 warp grid
    const int m0 = blockIdx.y * 128, n0 = blockIdx.x * 128;

    const int lrow = tid >> 1;
    const int lk = (tid & 1) * 16;
    const float* xp = X + (size_t)(m0 + lrow) * K + lk;
    const float* wp = W + (size_t)(n0 + lrow) * K + lk;
    float* xs = &Xs[lrow * GP + lk];
    float* ws = &Ws[lrow * GP + lk];

    float4 xr[4], wr[4];
#pragma unroll
    for (int i = 0; i < 4; i++) {
        xr[i] = *(const float4*)(xp + i * 4);
        wr[i] = *(const float4*)(wp + i * 4);
    }

    float acc[4][4][4] = {};

    for (int kb = 0; kb < K; kb += 32) {
        __syncthreads();
        {
            float4 o;
            o.x = tf32r(xr[0].x); o.y = tf32r(xr[1].x); o.z = tf32r(xr[0].y); o.w = tf32r(xr[1].y);
            *(float4*)(xs + 0) = o;
            o.x = tf32r(xr[0].z); o.y = tf32r(xr[1].z); o.z = tf32r(xr[0].w); o.w = tf32r(xr[1].w);
            *(float4*)(xs + 4) = o;
            o.x = tf32r(xr[2].x); o.y = tf32r(xr[3].x); o.z = tf32r(xr[2].y); o.w = tf32r(xr[3].y);
            *(float4*)(xs + 8) = o;
            o.x = tf32r(xr[2].z); o.y = tf32r(xr[3].z); o.z = tf32r(xr[2].w); o.w = tf32r(xr[3].w);
            *(float4*)(xs + 12) = o;
            o.x = tf32r(wr[0].x); o.y = tf32r(wr[1].x); o.z = tf32r(wr[0].y); o.w = tf32r(wr[1].y);
            *(float4*)(ws + 0) = o;
            o.x = tf32r(wr[0].z); o.y = tf32r(wr[1].z); o.z = tf32r(wr[0].w); o.w = tf32r(wr[1].w);
            *(float4*)(ws + 4) = o;
            o.x = tf32r(wr[2].x); o.y = tf32r(wr[3].x); o.z = tf32r(wr[2].y); o.w = tf32r(wr[3].y);
            *(float4*)(ws + 8) = o;
            o.x = tf32r(wr[2].z); o.y = tf32r(wr[3].z); o.z = tf32r(wr[2].w); o.w = tf32r(wr[3].w);
            *(float4*)(ws + 12) = o;
        }
        __syncthreads();

        if (kb + 32 < K) {
#pragma unroll
            for (int i = 0; i < 4; i++) {
                xr[i] = *(const float4*)(xp + kb + 32 + i * 4);
                wr[i] = *(const float4*)(wp + kb + 32 + i * 4);
            }
        }

#pragma unroll
        for (int ks = 0; ks < 4; ks++) {
            float2 al[4], ah[4], bf[4];
#pragma unroll
            for (int mt = 0; mt < 4; mt++) {
                int r = wy * 64 + mt * 16 + g;
                al[mt] = *(float2*)&Xs[r * GP + ks * 8 + 2 * tig];
                ah[mt] = *(float2*)&Xs[(r + 8) * GP + ks * 8 + 2 * tig];
            }
#pragma unroll
            for (int nt = 0; nt < 4; nt++)
                bf[nt] = *(float2*)&Ws[(wx * 32 + nt * 8 + g) * GP + ks * 8 + 2 * tig];
#pragma unroll
            for (int mt = 0; mt < 4; mt++)
#pragma unroll
                for (int nt = 0; nt < 4; nt++)
                    mma8(acc[mt][nt], al[mt].x, ah[mt].x, al[mt].y, ah[mt].y,
                         bf[nt].x, bf[nt].y);
        }
    }

#pragma unroll
    for (int nt = 0; nt < 4; nt++) {
        int c = n0 + wx * 32 + nt * 8 + 2 * tig;
        float b0v = bias[c], b1v = bias[c + 1];
#pragma unroll
        for (int mt = 0; mt < 4; mt++) {
            int r = m0 + wy * 64 + mt * 16 + g;
            float o[4];
            o[0] = acc[mt][nt][0] + b0v;
            o[1] = acc[mt][nt][1] + b1v;
            o[2] = acc[mt][nt][2] + b0v;
            o[3] = acc[mt][nt][3] + b1v;
            if (MODE == 2) {
#pragma unroll
                for (int i = 0; i < 4; i++) o[i] = tf32r(o[i] * 0.125f);
            } else if (MODE == 1) {
#pragma unroll
                for (int i = 0; i < 4; i++) o[i] = tf32r(o[i]);
            }
            float2 o0 = {o[0], o[1]};
            float2 o1 = {o[2], o[3]};
            *(float2*)&Y[(size_t)r * N + c] = o0;
            *(float2*)&Y[(size_t)(r + 8) * N + c] = o1;
        }
    }
}

// ---------------------------------------------------------------------------
// Attention v3: register-resident P, cp.async double-buffered K/V.
// Per block: 128 q rows x (head,batch). 8 warps, each owns 16 q rows fully.
// Q a-frags persistent in registers (loaded once from global; Q pre-scaled
// by 1/8 and tf32-rounded by the projection GEMM).
// Consistent-k-permutation: S C-frags feed PV A-frags directly (no shuffles).
// smem: K 2x64x72 + V 2x64x68 = 71,680 B -> 2 CTAs/SM.
// ---------------------------------------------------------------------------
#define KPITCH 72
#define VPITCH 68
#define KBUF (64 * KPITCH)      // 4608
#define VBUF (64 * VPITCH)      // 4352
#define OFF_V (2 * KBUF)        // 9216
#define ATT_SM ((OFF_V + 2 * VBUF) * 4)   // 71680 bytes

__global__ __launch_bounds__(256, 2) void attn_v3(
    const float* __restrict__ Q, const float* __restrict__ K,
    const float* __restrict__ V, const float* __restrict__ wmix,
    float* __restrict__ C)
{
    extern __shared__ float sm[];
    const unsigned sbase = (unsigned)__cvta_generic_to_shared(sm);

    const int tid = threadIdx.x;
    const int lane = tid & 31, w = tid >> 5;
    const int g = lane >> 2, tig = lane & 3;
    const int s0 = blockIdx.x * 128;
    const int h = blockIdx.y;
    const int b = blockIdx.z;
    const size_t base = (size_t)b * S_ * D_ + (size_t)h * DH_;

    const float* kgb = K + base;
    const float* vgb = V + base;

    // cp.async chunk assignment: 4 chunks of 16B for K, 4 for V, per tile
    const int crow0 = tid >> 4;          // rows tid>>4, +16, +32, +48
    const int cseg = (tid & 15) * 4;     // float offset within row

    // Prologue: tile 0 into buffer 0
    {
        const float* kg = kgb;
        const float* vg = vgb;
#pragma unroll
        for (int i = 0; i < 4; i++) {
            int row = crow0 + i * 16;
            cp16(sbase + (row * KPITCH + cseg) * 4, kg + (size_t)row * D_ + cseg);
            cp16(sbase + (OFF_V + row * VPITCH + cseg) * 4, vg + (size_t)row * D_ + cseg);
        }
        CP_COMMIT();
    }

    // Persistent Q fragments: rows w*16+g and +8, all 8 k-slabs
    float2 qa[8], qb[8];
    {
        const float* qp = Q + base + (size_t)(s0 + w * 16 + g) * D_;
        const float* qp8 = qp + 8 * D_;
#pragma unroll
        for (int ks = 0; ks < 8; ks++) {
            qa[ks] = *(const float2*)(qp + ks * 8 + 2 * tig);
            qb[ks] = *(const float2*)(qp8 + ks * 8 + 2 * tig);
        }
    }

    float e0 = __expf(wmix[0]), e1 = __expf(wmix[1]);
    float inv = 1.0f / (e0 + e1);
    const float mix0 = e0 * inv, mix1 = e1 * inv;

    float os[8][4] = {};
    float orl[8][4] = {};
    float lsum0 = 0.f, lsum1 = 0.f;

    for (int kt = 0; kt < 32; kt++) {
        if (kt) __syncthreads();   // all warps done with compute(kt-1)
        if (kt < 31) {
            const float* kg = kgb + (size_t)(kt + 1) * 64 * D_;
            const float* vg = vgb + (size_t)(kt + 1) * 64 * D_;
            unsigned sk = sbase + ((kt + 1) & 1) * KBUF * 4;
            unsigned sv = sbase + (OFF_V + ((kt + 1) & 1) * VBUF) * 4;
#pragma unroll
            for (int i = 0; i < 4; i++) {
                int row = crow0 + i * 16;
                cp16(sk + (row * KPITCH + cseg) * 4, kg + (size_t)row * D_ + cseg);
                cp16(sv + (row * VPITCH + cseg) * 4, vg + (size_t)row * D_ + cseg);
            }
            CP_COMMIT();
            CP_WAIT(1);
        } else {
            CP_WAIT(0);
        }
        __syncthreads();

        const float* Kb = sm + (kt & 1) * KBUF;
        const float* Vb = sm + OFF_V + (kt & 1) * VBUF;

#pragma unroll
        for (int nt = 0; nt < 8; nt++) {
            // S tile: rows (w*16+g, +8) x kv block nt*8
            float sc[4] = {0.f, 0.f, 0.f, 0.f};
#pragma unroll
            for (int ks = 0; ks < 8; ks++) {
                float2 bb = *(const float2*)&Kb[(nt * 8 + g) * KPITCH + ks * 8 + 2 * tig];
                mma8(sc, qa[ks].x, qb[ks].x, qa[ks].y, qb[ks].y, bb.x, bb.y);
            }

            // P fragments (C layout == PV A layout under consistent kv perm)
            float pe0 = __expf(sc[0]), pe1 = __expf(sc[1]);
            float pe2 = __expf(sc[2]), pe3 = __expf(sc[3]);
            lsum0 += pe0 + pe1;
            lsum1 += pe2 + pe3;
            float pq0 = sc[0] > 0.f ? mix1 * sc[0] * sc[0] : 0.f;
            float pq1 = sc[1] > 0.f ? mix1 * sc[1] * sc[1] : 0.f;
            float pq2 = sc[2] > 0.f ? mix1 * sc[2] * sc[2] : 0.f;
            float pq3 = sc[3] > 0.f ? mix1 * sc[3] * sc[3] : 0.f;
            pe0 = tf32r(pe0); pe1 = tf32r(pe1); pe2 = tf32r(pe2); pe3 = tf32r(pe3);
            pq0 = tf32r(pq0); pq1 = tf32r(pq1); pq2 = tf32r(pq2); pq3 = tf32r(pq3);

            // PV over this kv block for all 8 dh blocks
            const float* vb0 = Vb + (nt * 8 + 2 * tig) * VPITCH + g;
#pragma unroll
            for (int dt = 0; dt < 8; dt++) {
                float b0 = vb0[dt * 8];
                float b1 = vb0[VPITCH + dt * 8];
                mma8(os[dt], pe0, pe2, pe1, pe3, b0, b1);
                mma8(orl[dt], pq0, pq2, pq1, pq3, b0, b1);
            }
        }
    }

    // Row sums: lanes with same g (tig quad) hold disjoint column sets
    lsum0 += __shfl_xor_sync(0xffffffffu, lsum0, 1);
    lsum0 += __shfl_xor_sync(0xffffffffu, lsum0, 2);
    lsum1 += __shfl_xor_sync(0xffffffffu, lsum1, 1);
    lsum1 += __shfl_xor_sync(0xffffffffu, lsum1, 2);

    float f0 = mix0 / lsum0;
    float f1 = mix0 / lsum1;

    float* crow = C + base + (size_t)(s0 + w * 16 + g) * D_;
    float* crow8 = crow + 8 * D_;
#pragma unroll
    for (int dt = 0; dt < 8; dt++) {
        float2 o0 = {os[dt][0] * f0 + orl[dt][0], os[dt][1] * f0 + orl[dt][1]};
        float2 o1 = {os[dt][2] * f1 + orl[dt][2], os[dt][3] * f1 + orl[dt][3]};
        *(float2*)(crow + dt * 8 + 2 * tig) = o0;
        *(float2*)(crow8 + dt * 8 + 2 * tig) = o1;
    }
}

// ---------------------------------------------------------------------------
extern "C" void kernel_launch(void* const* d_in, const int* in_sizes, int n_in,
                              void* d_out, int out_size)
{
    const float* hs   = (const float*)d_in[0];
    const float* Wq   = (const float*)d_in[1];
    const float* bq   = (const float*)d_in[2];
    const float* Wk   = (const float*)d_in[3];
    const float* bk   = (const float*)d_in[4];
    const float* Wv   = (const float*)d_in[5];
    const float* bv   = (const float*)d_in[6];
    const float* Wo   = (const float*)d_in[7];
    const float* bo   = (const float*)d_in[8];
    const float* wmix = (const float*)d_in[9];
    float* out = (float*)d_out;

    float *q, *k, *v, *c;
    cudaGetSymbolAddress((void**)&q, g_Q);
    cudaGetSymbolAddress((void**)&k, g_K);
    cudaGetSymbolAddress((void**)&v, g_V);
    cudaGetSymbolAddress((void**)&c, g_C);

    dim3 gg(D_ / 128, M_TOT / 128);   // (6, 64)
    gemm_tf32<2><<<gg, 256>>>(hs, Wq, bq, q, M_TOT, D_, D_);   // Q: *0.125, tf32
    gemm_tf32<1><<<gg, 256>>>(hs, Wk, bk, k, M_TOT, D_, D_);   // K: tf32
    gemm_tf32<1><<<gg, 256>>>(hs, Wv, bv, v, M_TOT, D_, D_);   // V: tf32

    cudaFuncSetAttribute(attn_v3, cudaFuncAttributeMaxDynamicSharedMemorySize, ATT_SM);
    attn_v3<<<dim3(S_ / 128, H_, B_), 256, ATT_SM>>>(q, k, v, wmix, c);

    gemm_tf32<0><<<gg, 256>>>(c, Wo, bo, out, M_TOT, D_, D_);
}

// round 4
// speedup vs baseline: 3.4926x; 1.0787x over previous
#include <cuda_runtime.h>
#include <math.h>

#define B_ 4
#define S_ 2048
#define D_ 768
#define H_ 12
#define DH_ 64
#define M_TOT (B_ * S_)          // 8192
#define NELEM (M_TOT * D_)       // 6291456

__device__ float g_Q[NELEM];
__device__ float g_K[NELEM];
__device__ float g_V[NELEM];
__device__ float g_C[NELEM];

__device__ __forceinline__ float tf32r(float f) {
    unsigned u;
    asm("cvt.rna.tf32.f32 %0, %1;" : "=r"(u) : "f"(f));
    return __uint_as_float(u);
}

__device__ __forceinline__ void mma8(float* c, float a0, float a1, float a2, float a3,
                                     float b0, float b1) {
    asm volatile(
        "mma.sync.aligned.m16n8k8.row.col.f32.tf32.tf32.f32 "
        "{%0,%1,%2,%3},{%4,%5,%6,%7},{%8,%9},{%0,%1,%2,%3};\n"
        : "+f"(c[0]), "+f"(c[1]), "+f"(c[2]), "+f"(c[3])
        : "r"(__float_as_uint(a0)), "r"(__float_as_uint(a1)),
          "r"(__float_as_uint(a2)), "r"(__float_as_uint(a3)),
          "r"(__float_as_uint(b0)), "r"(__float_as_uint(b1)));
}

__device__ __forceinline__ void cp16(unsigned dst, const void* src) {
    asm volatile("cp.async.cg.shared.global [%0], [%1], 16;" :: "r"(dst), "l"(src));
}
#define CP_COMMIT() asm volatile("cp.async.commit_group;")
#define CP_WAIT(N) asm volatile("cp.async.wait_group %0;" :: "n"(N))

// ---------------------------------------------------------------------------
// GEMM core: Y[M,N] = X[M,K] @ W[N,K]^T + bias[N]  (tf32 mma, 128x128x32)
// mode 0: plain f32 out; mode 1: tf32-rounded (out*oscale).
// ---------------------------------------------------------------------------
#define GP 40

__device__ __forceinline__ void gemm_body(
    const float* __restrict__ X, const float* __restrict__ W,
    const float* __restrict__ bias, float* __restrict__ Y,
    int M, int N, int K, float oscale, int mode,
    float* Xs, float* Ws)
{
    const int tid = threadIdx.x;
    const int lane = tid & 31, wid = tid >> 5;
    const int g = lane >> 2, tig = lane & 3;
    const int wy = wid >> 2, wx = wid & 3;     // 2 x 4 warp grid
    const int m0 = blockIdx.y * 128, n0 = blockIdx.x * 128;

    const int lrow = tid >> 1;
    const int lk = (tid & 1) * 16;
    const float* xp = X + (size_t)(m0 + lrow) * K + lk;
    const float* wp = W + (size_t)(n0 + lrow) * K + lk;
    float* xs = &Xs[lrow * GP + lk];
    float* ws = &Ws[lrow * GP + lk];

    float4 xr[4], wr[4];
#pragma unroll
    for (int i = 0; i < 4; i++) {
        xr[i] = *(const float4*)(xp + i * 4);
        wr[i] = *(const float4*)(wp + i * 4);
    }

    float acc[4][4][4] = {};

    for (int kb = 0; kb < K; kb += 32) {
        __syncthreads();
        {
            float4 o;
            o.x = tf32r(xr[0].x); o.y = tf32r(xr[1].x); o.z = tf32r(xr[0].y); o.w = tf32r(xr[1].y);
            *(float4*)(xs + 0) = o;
            o.x = tf32r(xr[0].z); o.y = tf32r(xr[1].z); o.z = tf32r(xr[0].w); o.w = tf32r(xr[1].w);
            *(float4*)(xs + 4) = o;
            o.x = tf32r(xr[2].x); o.y = tf32r(xr[3].x); o.z = tf32r(xr[2].y); o.w = tf32r(xr[3].y);
            *(float4*)(xs + 8) = o;
            o.x = tf32r(xr[2].z); o.y = tf32r(xr[3].z); o.z = tf32r(xr[2].w); o.w = tf32r(xr[3].w);
            *(float4*)(xs + 12) = o;
            o.x = tf32r(wr[0].x); o.y = tf32r(wr[1].x); o.z = tf32r(wr[0].y); o.w = tf32r(wr[1].y);
            *(float4*)(ws + 0) = o;
            o.x = tf32r(wr[0].z); o.y = tf32r(wr[1].z); o.z = tf32r(wr[0].w); o.w = tf32r(wr[1].w);
            *(float4*)(ws + 4) = o;
            o.x = tf32r(wr[2].x); o.y = tf32r(wr[3].x); o.z = tf32r(wr[2].y); o.w = tf32r(wr[3].y);
            *(float4*)(ws + 8) = o;
            o.x = tf32r(wr[2].z); o.y = tf32r(wr[3].z); o.z = tf32r(wr[2].w); o.w = tf32r(wr[3].w);
            *(float4*)(ws + 12) = o;
        }
        __syncthreads();

        if (kb + 32 < K) {
#pragma unroll
            for (int i = 0; i < 4; i++) {
                xr[i] = *(const float4*)(xp + kb + 32 + i * 4);
                wr[i] = *(const float4*)(wp + kb + 32 + i * 4);
            }
        }

#pragma unroll
        for (int ks = 0; ks < 4; ks++) {
            float2 al[4], ah[4], bf[4];
#pragma unroll
            for (int mt = 0; mt < 4; mt++) {
                int r = wy * 64 + mt * 16 + g;
                al[mt] = *(float2*)&Xs[r * GP + ks * 8 + 2 * tig];
                ah[mt] = *(float2*)&Xs[(r + 8) * GP + ks * 8 + 2 * tig];
            }
#pragma unroll
            for (int nt = 0; nt < 4; nt++)
                bf[nt] = *(float2*)&Ws[(wx * 32 + nt * 8 + g) * GP + ks * 8 + 2 * tig];
#pragma unroll
            for (int mt = 0; mt < 4; mt++)
#pragma unroll
                for (int nt = 0; nt < 4; nt++)
                    mma8(acc[mt][nt], al[mt].x, ah[mt].x, al[mt].y, ah[mt].y,
                         bf[nt].x, bf[nt].y);
        }
    }

#pragma unroll
    for (int nt = 0; nt < 4; nt++) {
        int c = n0 + wx * 32 + nt * 8 + 2 * tig;
        float b0v = bias[c], b1v = bias[c + 1];
#pragma unroll
        for (int mt = 0; mt < 4; mt++) {
            int r = m0 + wy * 64 + mt * 16 + g;
            float o[4];
            o[0] = acc[mt][nt][0] + b0v;
            o[1] = acc[mt][nt][1] + b1v;
            o[2] = acc[mt][nt][2] + b0v;
            o[3] = acc[mt][nt][3] + b1v;
            if (mode == 1) {
#pragma unroll
                for (int i = 0; i < 4; i++) o[i] = tf32r(o[i] * oscale);
            }
            float2 o0 = {o[0], o[1]};
            float2 o1 = {o[2], o[3]};
            *(float2*)&Y[(size_t)r * N + c] = o0;
            *(float2*)&Y[(size_t)(r + 8) * N + c] = o1;
        }
    }
}

// Fused Q/K/V projections: blockIdx.z selects weight/bias/output.
__global__ __launch_bounds__(256, 2) void gemm_qkv(
    const float* __restrict__ X,
    const float* __restrict__ Wq, const float* __restrict__ bq, float* __restrict__ Yq,
    const float* __restrict__ Wk, const float* __restrict__ bk, float* __restrict__ Yk,
    const float* __restrict__ Wv, const float* __restrict__ bv, float* __restrict__ Yv)
{
    __shared__ float Xs[128 * GP];
    __shared__ float Ws[128 * GP];
    const float* W; const float* bi; float* Y; float sc;
    if (blockIdx.z == 0)      { W = Wq; bi = bq; Y = Yq; sc = 0.125f; }
    else if (blockIdx.z == 1) { W = Wk; bi = bk; Y = Yk; sc = 1.0f; }
    else                      { W = Wv; bi = bv; Y = Yv; sc = 1.0f; }
    gemm_body(X, W, bi, Y, M_TOT, D_, D_, sc, 1, Xs, Ws);
}

__global__ __launch_bounds__(256, 2) void gemm_out(
    const float* __restrict__ X, const float* __restrict__ W,
    const float* __restrict__ bias, float* __restrict__ Y)
{
    __shared__ float Xs[128 * GP];
    __shared__ float Ws[128 * GP];
    gemm_body(X, W, bias, Y, M_TOT, D_, D_, 1.0f, 0, Xs, Ws);
}

// ---------------------------------------------------------------------------
// Attention v4: register-resident P, cp.async double-buffered K/V, and
// software-pipelined S-computation: QK(nt+1)'s dependent MMA chain is issued
// between exp(nt) and PV(nt)'s independent MMAs so the tensor pipe stays fed.
// ---------------------------------------------------------------------------
#define KPITCH 72
#define VPITCH 68
#define KBUF (64 * KPITCH)      // 4608
#define VBUF (64 * VPITCH)      // 4352
#define OFF_V (2 * KBUF)        // 9216
#define ATT_SM ((OFF_V + 2 * VBUF) * 4)   // 71680 bytes

__global__ __launch_bounds__(256, 2) void attn_v4(
    const float* __restrict__ Q, const float* __restrict__ K,
    const float* __restrict__ V, const float* __restrict__ wmix,
    float* __restrict__ C)
{
    extern __shared__ float sm[];
    const unsigned sbase = (unsigned)__cvta_generic_to_shared(sm);

    const int tid = threadIdx.x;
    const int lane = tid & 31, w = tid >> 5;
    const int g = lane >> 2, tig = lane & 3;
    const int s0 = blockIdx.x * 128;
    const int h = blockIdx.y;
    const int b = blockIdx.z;
    const size_t base = (size_t)b * S_ * D_ + (size_t)h * DH_;

    const float* kgb = K + base;
    const float* vgb = V + base;

    const int crow0 = tid >> 4;
    const int cseg = (tid & 15) * 4;

    // Prologue: tile 0 into buffer 0
    {
#pragma unroll
        for (int i = 0; i < 4; i++) {
            int row = crow0 + i * 16;
            cp16(sbase + (row * KPITCH + cseg) * 4, kgb + (size_t)row * D_ + cseg);
            cp16(sbase + (OFF_V + row * VPITCH + cseg) * 4, vgb + (size_t)row * D_ + cseg);
        }
        CP_COMMIT();
    }

    // Persistent Q fragments
    float2 qa[8], qb[8];
    {
        const float* qp = Q + base + (size_t)(s0 + w * 16 + g) * D_;
        const float* qp8 = qp + 8 * D_;
#pragma unroll
        for (int ks = 0; ks < 8; ks++) {
            qa[ks] = *(const float2*)(qp + ks * 8 + 2 * tig);
            qb[ks] = *(const float2*)(qp8 + ks * 8 + 2 * tig);
        }
    }

    float e0 = __expf(wmix[0]), e1 = __expf(wmix[1]);
    float inv = 1.0f / (e0 + e1);
    const float mix0 = e0 * inv, mix1 = e1 * inv;

    float os[8][4] = {};
    float orl[8][4] = {};
    float lsum0 = 0.f, lsum1 = 0.f;

    for (int kt = 0; kt < 32; kt++) {
        if (kt) __syncthreads();
        if (kt < 31) {
            const float* kg = kgb + (size_t)(kt + 1) * 64 * D_;
            const float* vg = vgb + (size_t)(kt + 1) * 64 * D_;
            unsigned sk = sbase + ((kt + 1) & 1) * KBUF * 4;
            unsigned sv = sbase + (OFF_V + ((kt + 1) & 1) * VBUF) * 4;
#pragma unroll
            for (int i = 0; i < 4; i++) {
                int row = crow0 + i * 16;
                cp16(sk + (row * KPITCH + cseg) * 4, kg + (size_t)row * D_ + cseg);
                cp16(sv + (row * VPITCH + cseg) * 4, vg + (size_t)row * D_ + cseg);
            }
            CP_COMMIT();
            CP_WAIT(1);
        } else {
            CP_WAIT(0);
        }
        __syncthreads();

        const float* Kb = sm + (kt & 1) * KBUF;
        const float* Vb = sm + OFF_V + (kt & 1) * VBUF;

        float sc[2][4];
        // QK for nt = 0
        sc[0][0] = 0.f; sc[0][1] = 0.f; sc[0][2] = 0.f; sc[0][3] = 0.f;
#pragma unroll
        for (int ks = 0; ks < 8; ks++) {
            float2 bb = *(const float2*)&Kb[g * KPITCH + ks * 8 + 2 * tig];
            mma8(sc[0], qa[ks].x, qb[ks].x, qa[ks].y, qb[ks].y, bb.x, bb.y);
        }

#pragma unroll
        for (int nt = 0; nt < 8; nt++) {
            const int cur = nt & 1;

            // P fragments from sc[cur]
            float pe0 = __expf(sc[cur][0]), pe1 = __expf(sc[cur][1]);
            float pe2 = __expf(sc[cur][2]), pe3 = __expf(sc[cur][3]);
            lsum0 += pe0 + pe1;
            lsum1 += pe2 + pe3;
            float pq0 = sc[cur][0] > 0.f ? mix1 * sc[cur][0] * sc[cur][0] : 0.f;
            float pq1 = sc[cur][1] > 0.f ? mix1 * sc[cur][1] * sc[cur][1] : 0.f;
            float pq2 = sc[cur][2] > 0.f ? mix1 * sc[cur][2] * sc[cur][2] : 0.f;
            float pq3 = sc[cur][3] > 0.f ? mix1 * sc[cur][3] * sc[cur][3] : 0.f;
            pe0 = tf32r(pe0); pe1 = tf32r(pe1); pe2 = tf32r(pe2); pe3 = tf32r(pe3);
            pq0 = tf32r(pq0); pq1 = tf32r(pq1); pq2 = tf32r(pq2); pq3 = tf32r(pq3);

            // QK for nt+1 (dependent chain; overlaps with PV below)
            if (nt < 7) {
                const int nxt = cur ^ 1;
                sc[nxt][0] = 0.f; sc[nxt][1] = 0.f; sc[nxt][2] = 0.f; sc[nxt][3] = 0.f;
#pragma unroll
                for (int ks = 0; ks < 8; ks++) {
                    float2 bb = *(const float2*)&Kb[((nt + 1) * 8 + g) * KPITCH + ks * 8 + 2 * tig];
                    mma8(sc[nxt], qa[ks].x, qb[ks].x, qa[ks].y, qb[ks].y, bb.x, bb.y);
                }
            }

            // PV over kv block nt for all 8 dh blocks (16 independent MMAs)
            const float* vb0 = Vb + (nt * 8 + 2 * tig) * VPITCH + g;
#pragma unroll
            for (int dt = 0; dt < 8; dt++) {
                float b0 = vb0[dt * 8];
                float b1 = vb0[VPITCH + dt * 8];
                mma8(os[dt], pe0, pe2, pe1, pe3, b0, b1);
                mma8(orl[dt], pq0, pq2, pq1, pq3, b0, b1);
            }
        }
    }

    lsum0 += __shfl_xor_sync(0xffffffffu, lsum0, 1);
    lsum0 += __shfl_xor_sync(0xffffffffu, lsum0, 2);
    lsum1 += __shfl_xor_sync(0xffffffffu, lsum1, 1);
    lsum1 += __shfl_xor_sync(0xffffffffu, lsum1, 2);

    float f0 = mix0 / lsum0;
    float f1 = mix0 / lsum1;

    float* crow = C + base + (size_t)(s0 + w * 16 + g) * D_;
    float* crow8 = crow + 8 * D_;
#pragma unroll
    for (int dt = 0; dt < 8; dt++) {
        float2 o0 = {os[dt][0] * f0 + orl[dt][0], os[dt][1] * f0 + orl[dt][1]};
        float2 o1 = {os[dt][2] * f1 + orl[dt][2], os[dt][3] * f1 + orl[dt][3]};
        *(float2*)(crow + dt * 8 + 2 * tig) = o0;
        *(float2*)(crow8 + dt * 8 + 2 * tig) = o1;
    }
}

// ---------------------------------------------------------------------------
extern "C" void kernel_launch(void* const* d_in, const int* in_sizes, int n_in,
                              void* d_out, int out_size)
{
    const float* hs   = (const float*)d_in[0];
    const float* Wq   = (const float*)d_in[1];
    const float* bq   = (const float*)d_in[2];
    const float* Wk   = (const float*)d_in[3];
    const float* bk   = (const float*)d_in[4];
    const float* Wv   = (const float*)d_in[5];
    const float* bv   = (const float*)d_in[6];
    const float* Wo   = (const float*)d_in[7];
    const float* bo   = (const float*)d_in[8];
    const float* wmix = (const float*)d_in[9];
    float* out = (float*)d_out;

    float *q, *k, *v, *c;
    cudaGetSymbolAddress((void**)&q, g_Q);
    cudaGetSymbolAddress((void**)&k, g_K);
    cudaGetSymbolAddress((void**)&v, g_V);
    cudaGetSymbolAddress((void**)&c, g_C);

    gemm_qkv<<<dim3(D_ / 128, M_TOT / 128, 3), 256>>>(
        hs, Wq, bq, q, Wk, bk, k, Wv, bv, v);

    cudaFuncSetAttribute(attn_v4, cudaFuncAttributeMaxDynamicSharedMemorySize, ATT_SM);
    attn_v4<<<dim3(S_ / 128, H_, B_), 256, ATT_SM>>>(q, k, v, wmix, c);

    gemm_out<<<dim3(D_ / 128, M_TOT / 128), 256>>>(c, Wo, bo, out);
}

// round 6
// speedup vs baseline: 4.1364x; 1.1843x over previous
#include <cuda_runtime.h>
#include <math.h>
#include <stdint.h>

#define B_ 4
#define S_ 2048
#define D_ 768
#define H_ 12
#define DH_ 64
#define M_TOT (B_ * S_)          // 8192
#define NELEM (M_TOT * D_)       // 6291456
#define DD (D_ * D_)             // 589824

__device__ float g_Q[NELEM];
__device__ float g_K[NELEM];
__device__ float g_V[NELEM];
__device__ float g_C[NELEM];
__device__ float g_X[NELEM];
__device__ float g_W[4 * DD];

// ---------------------------------------------------------------------------
__device__ __forceinline__ float tf32r(float f) {
    unsigned u;
    asm("cvt.rna.tf32.f32 %0, %1;" : "=r"(u) : "f"(f));
    return __uint_as_float(u);
}

__device__ __forceinline__ void mma8(float* c, float a0, float a1, float a2, float a3,
                                     float b0, float b1) {
    asm volatile(
        "mma.sync.aligned.m16n8k8.row.col.f32.tf32.tf32.f32 "
        "{%0,%1,%2,%3},{%4,%5,%6,%7},{%8,%9},{%0,%1,%2,%3};\n"
        : "+f"(c[0]), "+f"(c[1]), "+f"(c[2]), "+f"(c[3])
        : "r"(__float_as_uint(a0)), "r"(__float_as_uint(a1)),
          "r"(__float_as_uint(a2)), "r"(__float_as_uint(a3)),
          "r"(__float_as_uint(b0)), "r"(__float_as_uint(b1)));
}

__device__ __forceinline__ void cp16(unsigned dst, const void* src) {
    asm volatile("cp.async.cg.shared.global [%0], [%1], 16;" :: "r"(dst), "l"(src));
}
#define CP_COMMIT() asm volatile("cp.async.commit_group;")
#define CP_WAIT(N) asm volatile("cp.async.wait_group %0;" :: "n"(N))

__device__ __forceinline__ unsigned smem_u32(const void* p) {
    unsigned a;
    asm("{ .reg .u64 t; cvta.to.shared.u64 t, %1; cvt.u32.u64 %0, t; }" : "=r"(a) : "l"(p));
    return a;
}

// ---------------------------------------------------------------------------
// Prepass: RNA-round + k-pair-permute hidden_states and 4 weights.
// Within each 8-k group, value k goes to position (k&3)*2 + (k>>2), so a
// float2 at position 2*tig yields (k=tig, k=tig+4) = the tf32 A/B fragment.
// ---------------------------------------------------------------------------
__global__ void round_pre_perm(const float* __restrict__ hs,
                               const float* __restrict__ Wq, const float* __restrict__ Wk,
                               const float* __restrict__ Wv, const float* __restrict__ Wo,
                               float* __restrict__ X, float* __restrict__ W)
{
    const int i = blockIdx.x * blockDim.x + threadIdx.x;
    const int stride = gridDim.x * blockDim.x;
    const int NGX = NELEM / 8;
    for (int gi = i; gi < NGX; gi += stride) {
        float4 v0 = *(const float4*)(hs + (size_t)gi * 8);
        float4 v1 = *(const float4*)(hs + (size_t)gi * 8 + 4);
        float4 a = {tf32r(v0.x), tf32r(v1.x), tf32r(v0.y), tf32r(v1.y)};
        float4 b = {tf32r(v0.z), tf32r(v1.z), tf32r(v0.w), tf32r(v1.w)};
        *(float4*)(X + (size_t)gi * 8) = a;
        *(float4*)(X + (size_t)gi * 8 + 4) = b;
    }
    const int NGW = DD / 8;
    const float* src[4] = {Wq, Wk, Wv, Wo};
#pragma unroll
    for (int w = 0; w < 4; w++) {
        const float* s = src[w];
        float* d = W + (size_t)w * DD;
        for (int gi = i; gi < NGW; gi += stride) {
            float4 v0 = *(const float4*)(s + (size_t)gi * 8);
            float4 v1 = *(const float4*)(s + (size_t)gi * 8 + 4);
            float4 a = {tf32r(v0.x), tf32r(v1.x), tf32r(v0.y), tf32r(v1.y)};
            float4 b = {tf32r(v0.z), tf32r(v1.z), tf32r(v0.w), tf32r(v1.w)};
            *(float4*)(d + (size_t)gi * 8) = a;
            *(float4*)(d + (size_t)gi * 8 + 4) = b;
        }
    }
}

// ---------------------------------------------------------------------------
// GEMM: Y[M,768] = X[M,768] @ W[768,768]^T + bias.  Inputs pre-rounded and
// pre-permuted -> pure cp.async double-buffer + LDS.64 fragments + HMMA.
// 128x128x32 tiles, 2x4 warp grid, 64x32 warp tile. blockIdx.z selects set.
// mode: 0 plain f32 out; 1 tf32r out; 2 tf32r(out*0.125).
// ---------------------------------------------------------------------------
#define GP 40
#define GSTG (128 * GP)              // 5120 floats per operand stage
#define GEMM_SM (4 * GSTG * 4)       // 81920 bytes (2 stages x A,B)

__global__ __launch_bounds__(256, 2) void gemm_cp(
    const float* __restrict__ X,
    const float* __restrict__ Wa, const float* __restrict__ ba, float* __restrict__ Ya, int ma,
    const float* __restrict__ Wb, const float* __restrict__ bb, float* __restrict__ Yb, int mb,
    const float* __restrict__ Wc, const float* __restrict__ bc, float* __restrict__ Yc, int mc)
{
    const float* W; const float* bi; float* Y; int mode;
    if (blockIdx.z == 0)      { W = Wa; bi = ba; Y = Ya; mode = ma; }
    else if (blockIdx.z == 1) { W = Wb; bi = bb; Y = Yb; mode = mb; }
    else                      { W = Wc; bi = bc; Y = Yc; mode = mc; }

    extern __shared__ float gs[];
    const unsigned sb = smem_u32(gs);

    const int tid = threadIdx.x;
    const int lane = tid & 31, wid = tid >> 5;
    const int g = lane >> 2, tig = lane & 3;
    const int wy = wid >> 2, wx = wid & 3;
    const int m0 = blockIdx.y * 128, n0 = blockIdx.x * 128;

#define G_LOAD(s_) do {                                                         \
        int st_ = (s_) & 1;                                                     \
        unsigned ab_ = sb + st_ * (2 * GSTG) * 4;                               \
        unsigned bb_ = ab_ + GSTG * 4;                                          \
        _Pragma("unroll")                                                       \
        for (int t_ = 0; t_ < 4; t_++) {                                        \
            int ch_ = tid + t_ * 256;                                           \
            int r_ = ch_ >> 3, c_ = ch_ & 7;                                    \
            cp16(ab_ + (r_ * GP + c_ * 4) * 4,                                  \
                 X + (size_t)(m0 + r_) * D_ + (s_) * 32 + c_ * 4);              \
            cp16(bb_ + (r_ * GP + c_ * 4) * 4,                                  \
                 W + (size_t)(n0 + r_) * D_ + (s_) * 32 + c_ * 4);              \
        }                                                                       \
        CP_COMMIT();                                                            \
    } while (0)

    G_LOAD(0);
    G_LOAD(1);

    float acc[4][4][4] = {};
    const int NSLAB = D_ / 32;   // 24

    for (int s = 0; s < NSLAB; s++) {
        if (s < NSLAB - 1) { CP_WAIT(1); } else { CP_WAIT(0); }
        __syncthreads();

        const float* Xs = gs + (s & 1) * (2 * GSTG);
        const float* Ws = Xs + GSTG;

#pragma unroll
        for (int ks = 0; ks < 4; ks++) {
            float2 al[4], ah[4], bf[4];
#pragma unroll
            for (int mt = 0; mt < 4; mt++) {
                int r = wy * 64 + mt * 16 + g;
                al[mt] = *(const float2*)&Xs[r * GP + ks * 8 + 2 * tig];
                ah[mt] = *(const float2*)&Xs[(r + 8) * GP + ks * 8 + 2 * tig];
            }
#pragma unroll
            for (int nt = 0; nt < 4; nt++)
                bf[nt] = *(const float2*)&Ws[(wx * 32 + nt * 8 + g) * GP + ks * 8 + 2 * tig];
#pragma unroll
            for (int mt = 0; mt < 4; mt++)
#pragma unroll
                for (int nt = 0; nt < 4; nt++)
                    mma8(acc[mt][nt], al[mt].x, ah[mt].x, al[mt].y, ah[mt].y,
                         bf[nt].x, bf[nt].y);
        }
        __syncthreads();
        if (s + 2 < NSLAB) G_LOAD(s + 2);
    }

#pragma unroll
    for (int nt = 0; nt < 4; nt++) {
        int c = n0 + wx * 32 + nt * 8 + 2 * tig;
        float b0v = bi[c], b1v = bi[c + 1];
#pragma unroll
        for (int mt = 0; mt < 4; mt++) {
            int r = m0 + wy * 64 + mt * 16 + g;
            float o[4];
            o[0] = acc[mt][nt][0] + b0v;
            o[1] = acc[mt][nt][1] + b1v;
            o[2] = acc[mt][nt][2] + b0v;
            o[3] = acc[mt][nt][3] + b1v;
            if (mode == 2) {
#pragma unroll
                for (int i = 0; i < 4; i++) o[i] = tf32r(o[i] * 0.125f);
            } else if (mode == 1) {
#pragma unroll
                for (int i = 0; i < 4; i++) o[i] = tf32r(o[i]);
            }
            float2 o0 = {o[0], o[1]};
            float2 o1 = {o[2], o[3]};
            *(float2*)&Y[(size_t)r * D_ + c] = o0;
            *(float2*)&Y[(size_t)(r + 8) * D_ + c] = o1;
        }
    }
}

// ---------------------------------------------------------------------------
// Attention v4 (proven): register-resident P, cp.async double-buffered K/V,
// software-pipelined S. Epilogue now writes ctx tf32-rounded in the k-paired
// permuted layout so the out-projection GEMM consumes it via cp.async.
// ---------------------------------------------------------------------------
#define KPITCH 72
#define VPITCH 68
#define KBUF (64 * KPITCH)
#define VBUF (64 * VPITCH)
#define OFF_V (2 * KBUF)
#define ATT_SM ((OFF_V + 2 * VBUF) * 4)   // 71680 bytes

__global__ __launch_bounds__(256, 2) void attn_v4(
    const float* __restrict__ Q, const float* __restrict__ K,
    const float* __restrict__ V, const float* __restrict__ wmix,
    float* __restrict__ C)
{
    extern __shared__ float sm[];
    const unsigned sbase = smem_u32(sm);

    const int tid = threadIdx.x;
    const int lane = tid & 31, w = tid >> 5;
    const int g = lane >> 2, tig = lane & 3;
    const int s0 = blockIdx.x * 128;
    const int h = blockIdx.y;
    const int b = blockIdx.z;
    const size_t base = (size_t)b * S_ * D_ + (size_t)h * DH_;

    const float* kgb = K + base;
    const float* vgb = V + base;

    const int crow0 = tid >> 4;
    const int cseg = (tid & 15) * 4;

    {
#pragma unroll
        for (int i = 0; i < 4; i++) {
            int row = crow0 + i * 16;
            cp16(sbase + (row * KPITCH + cseg) * 4, kgb + (size_t)row * D_ + cseg);
            cp16(sbase + (OFF_V + row * VPITCH + cseg) * 4, vgb + (size_t)row * D_ + cseg);
        }
        CP_COMMIT();
    }

    float2 qa[8], qb[8];
    {
        const float* qp = Q + base + (size_t)(s0 + w * 16 + g) * D_;
        const float* qp8 = qp + 8 * D_;
#pragma unroll
        for (int ks = 0; ks < 8; ks++) {
            qa[ks] = *(const float2*)(qp + ks * 8 + 2 * tig);
            qb[ks] = *(const float2*)(qp8 + ks * 8 + 2 * tig);
        }
    }

    float e0 = __expf(wmix[0]), e1 = __expf(wmix[1]);
    float inv = 1.0f / (e0 + e1);
    const float mix0 = e0 * inv, mix1 = e1 * inv;

    float os[8][4] = {};
    float orl[8][4] = {};
    float lsum0 = 0.f, lsum1 = 0.f;

    for (int kt = 0; kt < 32; kt++) {
        if (kt) __syncthreads();
        if (kt < 31) {
            const float* kg = kgb + (size_t)(kt + 1) * 64 * D_;
            const float* vg = vgb + (size_t)(kt + 1) * 64 * D_;
            unsigned sk = sbase + ((kt + 1) & 1) * KBUF * 4;
            unsigned sv = sbase + (OFF_V + ((kt + 1) & 1) * VBUF) * 4;
#pragma unroll
            for (int i = 0; i < 4; i++) {
                int row = crow0 + i * 16;
                cp16(sk + (row * KPITCH + cseg) * 4, kg + (size_t)row * D_ + cseg);
                cp16(sv + (row * VPITCH + cseg) * 4, vg + (size_t)row * D_ + cseg);
            }
            CP_COMMIT();
            CP_WAIT(1);
        } else {
            CP_WAIT(0);
        }
        __syncthreads();

        const float* Kb = sm + (kt & 1) * KBUF;
        const float* Vb = sm + OFF_V + (kt & 1) * VBUF;

        float sc[2][4];
        sc[0][0] = 0.f; sc[0][1] = 0.f; sc[0][2] = 0.f; sc[0][3] = 0.f;
#pragma unroll
        for (int ks = 0; ks < 8; ks++) {
            float2 bb = *(const float2*)&Kb[g * KPITCH + ks * 8 + 2 * tig];
            mma8(sc[0], qa[ks].x, qb[ks].x, qa[ks].y, qb[ks].y, bb.x, bb.y);
        }

#pragma unroll
        for (int nt = 0; nt < 8; nt++) {
            const int cur = nt & 1;

            float pe0 = __expf(sc[cur][0]), pe1 = __expf(sc[cur][1]);
            float pe2 = __expf(sc[cur][2]), pe3 = __expf(sc[cur][3]);
            lsum0 += pe0 + pe1;
            lsum1 += pe2 + pe3;
            float pq0 = sc[cur][0] > 0.f ? mix1 * sc[cur][0] * sc[cur][0] : 0.f;
            float pq1 = sc[cur][1] > 0.f ? mix1 * sc[cur][1] * sc[cur][1] : 0.f;
            float pq2 = sc[cur][2] > 0.f ? mix1 * sc[cur][2] * sc[cur][2] : 0.f;
            float pq3 = sc[cur][3] > 0.f ? mix1 * sc[cur][3] * sc[cur][3] : 0.f;
            pe0 = tf32r(pe0); pe1 = tf32r(pe1); pe2 = tf32r(pe2); pe3 = tf32r(pe3);
            pq0 = tf32r(pq0); pq1 = tf32r(pq1); pq2 = tf32r(pq2); pq3 = tf32r(pq3);

            if (nt < 7) {
                const int nxt = cur ^ 1;
                sc[nxt][0] = 0.f; sc[nxt][1] = 0.f; sc[nxt][2] = 0.f; sc[nxt][3] = 0.f;
#pragma unroll
                for (int ks = 0; ks < 8; ks++) {
                    float2 bb = *(const float2*)&Kb[((nt + 1) * 8 + g) * KPITCH + ks * 8 + 2 * tig];
                    mma8(sc[nxt], qa[ks].x, qb[ks].x, qa[ks].y, qb[ks].y, bb.x, bb.y);
                }
            }

            const float* vb0 = Vb + (nt * 8 + 2 * tig) * VPITCH + g;
#pragma unroll
            for (int dt = 0; dt < 8; dt++) {
                float b0 = vb0[dt * 8];
                float b1 = vb0[VPITCH + dt * 8];
                mma8(os[dt], pe0, pe2, pe1, pe3, b0, b1);
                mma8(orl[dt], pq0, pq2, pq1, pq3, b0, b1);
            }
        }
    }

    lsum0 += __shfl_xor_sync(0xffffffffu, lsum0, 1);
    lsum0 += __shfl_xor_sync(0xffffffffu, lsum0, 2);
    lsum1 += __shfl_xor_sync(0xffffffffu, lsum1, 1);
    lsum1 += __shfl_xor_sync(0xffffffffu, lsum1, 2);

    float f0 = mix0 / lsum0;
    float f1 = mix0 / lsum1;

    // Permuted positions within each 8-col block: pos(c) = (c&3)*2 + (c>>2)
    const int c0n = 2 * tig, c1n = 2 * tig + 1;
    const int p0 = (c0n & 3) * 2 + (c0n >> 2);
    const int p1 = (c1n & 3) * 2 + (c1n >> 2);

    float* crow = C + base + (size_t)(s0 + w * 16 + g) * D_;
    float* crow8 = crow + 8 * D_;
#pragma unroll
    for (int dt = 0; dt < 8; dt++) {
        crow[dt * 8 + p0]  = tf32r(os[dt][0] * f0 + orl[dt][0]);
        crow[dt * 8 + p1]  = tf32r(os[dt][1] * f0 + orl[dt][1]);
        crow8[dt * 8 + p0] = tf32r(os[dt][2] * f1 + orl[dt][2]);
        crow8[dt * 8 + p1] = tf32r(os[dt][3] * f1 + orl[dt][3]);
    }
}

// ---------------------------------------------------------------------------
extern "C" void kernel_launch(void* const* d_in, const int* in_sizes, int n_in,
                              void* d_out, int out_size)
{
    const float* hs   = (const float*)d_in[0];
    const float* Wq   = (const float*)d_in[1];
    const float* bq   = (const float*)d_in[2];
    const float* Wk   = (const float*)d_in[3];
    const float* bk   = (const float*)d_in[4];
    const float* Wv   = (const float*)d_in[5];
    const float* bv   = (const float*)d_in[6];
    const float* Wo   = (const float*)d_in[7];
    const float* bo   = (const float*)d_in[8];
    const float* wmix = (const float*)d_in[9];
    float* out = (float*)d_out;

    float *q, *k, *v, *c, *x, *wbuf;
    cudaGetSymbolAddress((void**)&q, g_Q);
    cudaGetSymbolAddress((void**)&k, g_K);
    cudaGetSymbolAddress((void**)&v, g_V);
    cudaGetSymbolAddress((void**)&c, g_C);
    cudaGetSymbolAddress((void**)&x, g_X);
    cudaGetSymbolAddress((void**)&wbuf, g_W);

    round_pre_perm<<<2048, 256>>>(hs, Wq, Wk, Wv, Wo, x, wbuf);

    cudaFuncSetAttribute(gemm_cp, cudaFuncAttributeMaxDynamicSharedMemorySize, GEMM_SM);
    gemm_cp<<<dim3(D_ / 128, M_TOT / 128, 3), 256, GEMM_SM>>>(
        x,
        wbuf + 0 * (size_t)DD, bq, q, 2,
        wbuf + 1 * (size_t)DD, bk, k, 1,
        wbuf + 2 * (size_t)DD, bv, v, 1);

    cudaFuncSetAttribute(attn_v4, cudaFuncAttributeMaxDynamicSharedMemorySize, ATT_SM);
    attn_v4<<<dim3(S_ / 128, H_, B_), 256, ATT_SM>>>(q, k, v, wmix, c);

    gemm_cp<<<dim3(D_ / 128, M_TOT / 128, 1), 256, GEMM_SM>>>(
        c,
        wbuf + 3 * (size_t)DD, bo, out, 0,
        wbuf + 3 * (size_t)DD, bo, out, 0,
        wbuf + 3 * (size_t)DD, bo, out, 0);
}

// round 7
// speedup vs baseline: 7.1993x; 1.7405x over previous
#include <cuda_runtime.h>
#include <cuda_fp16.h>
#include <math.h>
#include <stdint.h>

#define B_ 4
#define S_ 2048
#define D_ 768
#define H_ 12
#define DH_ 64
#define M_TOT (B_ * S_)          // 8192
#define NELEM (M_TOT * D_)       // 6291456
#define DD (D_ * D_)             // 589824

typedef unsigned short u16;
typedef unsigned int u32;

__device__ u16 g_Q[NELEM];
__device__ u16 g_K[NELEM];
__device__ u16 g_V[NELEM];
__device__ u16 g_C[NELEM];
__device__ u16 g_X[NELEM];
__device__ u16 g_W[4 * DD];

// ---------------------------------------------------------------------------
__device__ __forceinline__ u32 h2pack(float lo, float hi) {
    u32 r;
    asm("cvt.rn.f16x2.f32 %0, %1, %2;" : "=r"(r) : "f"(hi), "f"(lo));
    return r;
}

__device__ __forceinline__ void mma16(float* c, u32 a0, u32 a1, u32 a2, u32 a3,
                                      u32 b0, u32 b1) {
    asm volatile(
        "mma.sync.aligned.m16n8k16.row.col.f32.f16.f16.f32 "
        "{%0,%1,%2,%3},{%4,%5,%6,%7},{%8,%9},{%0,%1,%2,%3};\n"
        : "+f"(c[0]), "+f"(c[1]), "+f"(c[2]), "+f"(c[3])
        : "r"(a0), "r"(a1), "r"(a2), "r"(a3), "r"(b0), "r"(b1));
}

__device__ __forceinline__ void ldsm2t(u32& r0, u32& r1, u32 addr) {
    asm volatile("ldmatrix.sync.aligned.m8n8.x2.trans.shared.b16 {%0,%1}, [%2];"
                 : "=r"(r0), "=r"(r1) : "r"(addr));
}

__device__ __forceinline__ void cp16(unsigned dst, const void* src) {
    asm volatile("cp.async.cg.shared.global [%0], [%1], 16;" :: "r"(dst), "l"(src));
}
#define CP_COMMIT() asm volatile("cp.async.commit_group;")
#define CP_WAIT(N) asm volatile("cp.async.wait_group %0;" :: "n"(N))

__device__ __forceinline__ unsigned smem_u32(const void* p) {
    unsigned a;
    asm("{ .reg .u64 t; cvta.to.shared.u64 t, %1; cvt.u32.u64 %0, t; }" : "=r"(a) : "l"(p));
    return a;
}

// ---------------------------------------------------------------------------
// Prepass: RN-round hidden_states and 4 weights to fp16.
// ---------------------------------------------------------------------------
__global__ void to_half_pre(const float* __restrict__ hs,
                            const float* __restrict__ Wq, const float* __restrict__ Wk,
                            const float* __restrict__ Wv, const float* __restrict__ Wo,
                            u16* __restrict__ X, u16* __restrict__ W)
{
    const int i = blockIdx.x * blockDim.x + threadIdx.x;
    const int stride = gridDim.x * blockDim.x;
    for (int j = i; j < NELEM / 4; j += stride) {
        float4 v = ((const float4*)hs)[j];
        uint2 o = {h2pack(v.x, v.y), h2pack(v.z, v.w)};
        ((uint2*)X)[j] = o;
    }
    const float* src[4] = {Wq, Wk, Wv, Wo};
#pragma unroll
    for (int w = 0; w < 4; w++) {
        const float4* s = (const float4*)src[w];
        uint2* d = (uint2*)(W + (size_t)w * DD);
        for (int j = i; j < DD / 4; j += stride) {
            float4 v = s[j];
            uint2 o = {h2pack(v.x, v.y), h2pack(v.z, v.w)};
            d[j] = o;
        }
    }
}

// ---------------------------------------------------------------------------
// fp16 GEMM body: Y[M,768] = X[M,768] @ W[768,768]^T + bias.
// 128x128 tiles, BK=64 halves (128B rows), 2x4 warp grid, m16n8k16 HMMA.
// half_out: 1 -> fp16 output scaled by oscale; 0 -> f32 output.
// ---------------------------------------------------------------------------
#define GPH 72                      // smem pitch in halves (144 B)
#define GSTGH (128 * GPH)           // halves per operand stage
#define GEMM_SM (GSTGH * 2 * 2 * 2) // 73728 bytes

__device__ __forceinline__ void gemm_h_body(
    const u16* __restrict__ X, const u16* __restrict__ W,
    const float* __restrict__ bi, void* __restrict__ Yp,
    int half_out, float oscale, u16* gsm)
{
    const unsigned sb = smem_u32(gsm);
    const int tid = threadIdx.x;
    const int lane = tid & 31, wid = tid >> 5;
    const int g = lane >> 2, tig = lane & 3;
    const int wy = wid >> 2, wx = wid & 3;
    const int m0 = blockIdx.y * 128, n0 = blockIdx.x * 128;

#define GH_LOAD(s_) do {                                                        \
        int st_ = (s_) & 1;                                                     \
        unsigned ab_ = sb + st_ * (2 * GSTGH) * 2;                              \
        unsigned bb_ = ab_ + GSTGH * 2;                                         \
        _Pragma("unroll")                                                       \
        for (int u_ = 0; u_ < 4; u_++) {                                        \
            int ch_ = tid + u_ * 256;                                           \
            int r_ = ch_ >> 3, c_ = ch_ & 7;                                    \
            cp16(ab_ + r_ * 144 + c_ * 16,                                      \
                 X + (size_t)(m0 + r_) * D_ + (s_) * 64 + c_ * 8);              \
            cp16(bb_ + r_ * 144 + c_ * 16,                                      \
                 W + (size_t)(n0 + r_) * D_ + (s_) * 64 + c_ * 8);              \
        }                                                                       \
        CP_COMMIT();                                                            \
    } while (0)

    GH_LOAD(0);
    GH_LOAD(1);

    float acc[4][4][4] = {};
    const int NSLAB = D_ / 64;   // 12

    for (int s = 0; s < NSLAB; s++) {
        if (s < NSLAB - 1) { CP_WAIT(1); } else { CP_WAIT(0); }
        __syncthreads();

        const u16* Xs = gsm + (s & 1) * (2 * GSTGH);
        const u16* Ws = Xs + GSTGH;

#pragma unroll
        for (int ks = 0; ks < 4; ks++) {
            u32 a[4][4], b[4][2];
#pragma unroll
            for (int mt = 0; mt < 4; mt++) {
                int r = wy * 64 + mt * 16 + g;
                a[mt][0] = *(const u32*)&Xs[r * GPH + ks * 16 + 2 * tig];
                a[mt][1] = *(const u32*)&Xs[(r + 8) * GPH + ks * 16 + 2 * tig];
                a[mt][2] = *(const u32*)&Xs[r * GPH + ks * 16 + 8 + 2 * tig];
                a[mt][3] = *(const u32*)&Xs[(r + 8) * GPH + ks * 16 + 8 + 2 * tig];
            }
#pragma unroll
            for (int nt = 0; nt < 4; nt++) {
                int r = wx * 32 + nt * 8 + g;
                b[nt][0] = *(const u32*)&Ws[r * GPH + ks * 16 + 2 * tig];
                b[nt][1] = *(const u32*)&Ws[r * GPH + ks * 16 + 8 + 2 * tig];
            }
#pragma unroll
            for (int mt = 0; mt < 4; mt++)
#pragma unroll
                for (int nt = 0; nt < 4; nt++)
                    mma16(acc[mt][nt], a[mt][0], a[mt][1], a[mt][2], a[mt][3],
                          b[nt][0], b[nt][1]);
        }
        __syncthreads();
        if (s + 2 < NSLAB) GH_LOAD(s + 2);
    }

#pragma unroll
    for (int nt = 0; nt < 4; nt++) {
        int c = n0 + wx * 32 + nt * 8 + 2 * tig;
        float b0v = bi[c], b1v = bi[c + 1];
#pragma unroll
        for (int mt = 0; mt < 4; mt++) {
            int r = m0 + wy * 64 + mt * 16 + g;
            float o0 = acc[mt][nt][0] + b0v;
            float o1 = acc[mt][nt][1] + b1v;
            float o2 = acc[mt][nt][2] + b0v;
            float o3 = acc[mt][nt][3] + b1v;
            if (half_out) {
                u16* Yh = (u16*)Yp;
                *(u32*)&Yh[(size_t)r * D_ + c] = h2pack(o0 * oscale, o1 * oscale);
                *(u32*)&Yh[(size_t)(r + 8) * D_ + c] = h2pack(o2 * oscale, o3 * oscale);
            } else {
                float* Yf = (float*)Yp;
                float2 q0 = {o0, o1}, q1 = {o2, o3};
                *(float2*)&Yf[(size_t)r * D_ + c] = q0;
                *(float2*)&Yf[(size_t)(r + 8) * D_ + c] = q1;
            }
        }
    }
#undef GH_LOAD
}

__global__ __launch_bounds__(256, 2) void gemm_qkv_h(
    const u16* __restrict__ X,
    const u16* __restrict__ Wh, const float* __restrict__ bq,
    const float* __restrict__ bk, const float* __restrict__ bv,
    u16* __restrict__ Yq, u16* __restrict__ Yk, u16* __restrict__ Yv)
{
    extern __shared__ u16 gsm[];
    const u16* W; const float* bi; u16* Y; float sc;
    if (blockIdx.z == 0)      { W = Wh;          bi = bq; Y = Yq; sc = 0.125f; }
    else if (blockIdx.z == 1) { W = Wh + DD;     bi = bk; Y = Yk; sc = 1.0f; }
    else                      { W = Wh + 2 * DD; bi = bv; Y = Yv; sc = 1.0f; }
    gemm_h_body(X, W, bi, Y, 1, sc, gsm);
}

__global__ __launch_bounds__(256, 2) void gemm_out_h(
    const u16* __restrict__ X, const u16* __restrict__ Wh,
    const float* __restrict__ bo, float* __restrict__ Y)
{
    extern __shared__ u16 gsm[];
    gemm_h_body(X, Wh, bo, Y, 0, 1.0f, gsm);
}

// ---------------------------------------------------------------------------
// Attention fp16: per block 128 q rows x (h,b); 8 warps x 16 q rows.
// K/V natural [kv][dh] half in smem (cp.async double-buffered, pitch 72 halves).
// QK: m16n8k16, B-frags = plain b32 loads from K.
// PV: m16n8k16, B-frags via ldmatrix.x2.trans on natural V; A-frags packed
// from S C-frags (even 8-block -> k0-7, odd 8-block -> k8-15).
// ---------------------------------------------------------------------------
#define KPH 72                      // pitch halves, 144 B
#define KBUFB (64 * 144)            // 9216 B per tile buffer
#define OFF_VB (2 * KBUFB)          // 18432
#define ATT_SM (OFF_VB + 2 * KBUFB) // 36864 B

__global__ __launch_bounds__(256, 2) void attn_h(
    const u16* __restrict__ Q, const u16* __restrict__ K,
    const u16* __restrict__ V, const float* __restrict__ wmix,
    u16* __restrict__ C)
{
    extern __shared__ u16 sm[];
    const unsigned sbase = smem_u32(sm);

    const int tid = threadIdx.x;
    const int lane = tid & 31, w = tid >> 5;
    const int g = lane >> 2, tig = lane & 3;
    const int s0 = blockIdx.x * 128;
    const int h = blockIdx.y;
    const int b = blockIdx.z;
    const size_t base = (size_t)b * S_ * D_ + (size_t)h * DH_;

    const u16* kgb = K + base;
    const u16* vgb = V + base;

    const int lrow = tid >> 3;       // 0..31
    const int lseg = tid & 7;        // 16B segment

#define ATT_LOAD(kt_, sk_, sv_) do {                                            \
        const u16* kg_ = kgb + (size_t)(kt_) * 64 * D_;                         \
        const u16* vg_ = vgb + (size_t)(kt_) * 64 * D_;                         \
        _Pragma("unroll")                                                       \
        for (int u_ = 0; u_ < 2; u_++) {                                        \
            int row_ = lrow + u_ * 32;                                          \
            cp16((sk_) + row_ * 144 + lseg * 16, kg_ + (size_t)row_ * D_ + lseg * 8); \
            cp16((sv_) + row_ * 144 + lseg * 16, vg_ + (size_t)row_ * D_ + lseg * 8); \
        }                                                                       \
        CP_COMMIT();                                                            \
    } while (0)

    ATT_LOAD(0, sbase, sbase + OFF_VB);

    // Persistent Q fragments: rows w*16+g / +8, 4 k16-groups
    u32 qA[4][4];
    {
        const u16* qp = Q + base + (size_t)(s0 + w * 16 + g) * D_;
        const u16* qp8 = qp + 8 * D_;
#pragma unroll
        for (int ks = 0; ks < 4; ks++) {
            qA[ks][0] = *(const u32*)(qp + ks * 16 + 2 * tig);
            qA[ks][1] = *(const u32*)(qp8 + ks * 16 + 2 * tig);
            qA[ks][2] = *(const u32*)(qp + ks * 16 + 8 + 2 * tig);
            qA[ks][3] = *(const u32*)(qp8 + ks * 16 + 8 + 2 * tig);
        }
    }

    float e0 = __expf(wmix[0]), e1 = __expf(wmix[1]);
    float inv = 1.0f / (e0 + e1);
    const float mix0 = e0 * inv, mix1 = e1 * inv;

    float os[8][4] = {};
    float orl[8][4] = {};
    float lsum0 = 0.f, lsum1 = 0.f;

    for (int kt = 0; kt < 32; kt++) {
        if (kt) __syncthreads();
        if (kt < 31) {
            unsigned sk = sbase + ((kt + 1) & 1) * KBUFB;
            unsigned sv = sbase + OFF_VB + ((kt + 1) & 1) * KBUFB;
            ATT_LOAD(kt + 1, sk, sv);
            CP_WAIT(1);
        } else {
            CP_WAIT(0);
        }
        __syncthreads();

        const u16* Kb = sm + (kt & 1) * (KBUFB / 2);
        const unsigned svb = sbase + OFF_VB + (kt & 1) * KBUFB;

#pragma unroll
        for (int kvg = 0; kvg < 4; kvg++) {
            // --- QK: two 8-wide n-blocks (kv low/high 8 of this 16-group) ---
            float sce[4] = {0.f, 0.f, 0.f, 0.f};
            float sco[4] = {0.f, 0.f, 0.f, 0.f};
            const u16* krow_e = Kb + (kvg * 16 + g) * KPH;
            const u16* krow_o = krow_e + 8 * KPH;
#pragma unroll
            for (int ks = 0; ks < 4; ks++) {
                u32 be0 = *(const u32*)(krow_e + ks * 16 + 2 * tig);
                u32 be1 = *(const u32*)(krow_e + ks * 16 + 8 + 2 * tig);
                mma16(sce, qA[ks][0], qA[ks][1], qA[ks][2], qA[ks][3], be0, be1);
                u32 bo0 = *(const u32*)(krow_o + ks * 16 + 2 * tig);
                u32 bo1 = *(const u32*)(krow_o + ks * 16 + 8 + 2 * tig);
                mma16(sco, qA[ks][0], qA[ks][1], qA[ks][2], qA[ks][3], bo0, bo1);
            }

            // --- exp / relu^2, pack PV A-frags ---
            float pe_e0 = __expf(sce[0]), pe_e1 = __expf(sce[1]);
            float pe_e2 = __expf(sce[2]), pe_e3 = __expf(sce[3]);
            float pe_o0 = __expf(sco[0]), pe_o1 = __expf(sco[1]);
            float pe_o2 = __expf(sco[2]), pe_o3 = __expf(sco[3]);
            lsum0 += pe_e0 + pe_e1 + pe_o0 + pe_o1;
            lsum1 += pe_e2 + pe_e3 + pe_o2 + pe_o3;

            float pq_e0 = sce[0] > 0.f ? mix1 * sce[0] * sce[0] : 0.f;
            float pq_e1 = sce[1] > 0.f ? mix1 * sce[1] * sce[1] : 0.f;
            float pq_e2 = sce[2] > 0.f ? mix1 * sce[2] * sce[2] : 0.f;
            float pq_e3 = sce[3] > 0.f ? mix1 * sce[3] * sce[3] : 0.f;
            float pq_o0 = sco[0] > 0.f ? mix1 * sco[0] * sco[0] : 0.f;
            float pq_o1 = sco[1] > 0.f ? mix1 * sco[1] * sco[1] : 0.f;
            float pq_o2 = sco[2] > 0.f ? mix1 * sco[2] * sco[2] : 0.f;
            float pq_o3 = sco[3] > 0.f ? mix1 * sco[3] * sco[3] : 0.f;

            u32 ape0 = h2pack(pe_e0, pe_e1);   // row g,   k 2tig..+1
            u32 ape1 = h2pack(pe_e2, pe_e3);   // row g+8, k 2tig..+1
            u32 ape2 = h2pack(pe_o0, pe_o1);   // row g,   k 8+2tig..+1
            u32 ape3 = h2pack(pe_o2, pe_o3);   // row g+8, k 8+2tig..+1
            u32 apq0 = h2pack(pq_e0, pq_e1);
            u32 apq1 = h2pack(pq_e2, pq_e3);
            u32 apq2 = h2pack(pq_o0, pq_o1);
            u32 apq3 = h2pack(pq_o2, pq_o3);

            // --- PV: ldmatrix.x2.trans B-frags from natural V ---
            const unsigned vrow = svb + (kvg * 16 + (lane & 15)) * 144;
#pragma unroll
            for (int dt = 0; dt < 8; dt++) {
                u32 vb0, vb1;
                ldsm2t(vb0, vb1, vrow + dt * 16);
                mma16(os[dt], ape0, ape1, ape2, ape3, vb0, vb1);
                mma16(orl[dt], apq0, apq1, apq2, apq3, vb0, vb1);
            }
        }
    }

    lsum0 += __shfl_xor_sync(0xffffffffu, lsum0, 1);
    lsum0 += __shfl_xor_sync(0xffffffffu, lsum0, 2);
    lsum1 += __shfl_xor_sync(0xffffffffu, lsum1, 1);
    lsum1 += __shfl_xor_sync(0xffffffffu, lsum1, 2);

    float f0 = mix0 / lsum0;
    float f1 = mix0 / lsum1;

    u16* crow = C + base + (size_t)(s0 + w * 16 + g) * D_;
    u16* crow8 = crow + 8 * D_;
#pragma unroll
    for (int dt = 0; dt < 8; dt++) {
        *(u32*)&crow[dt * 8 + 2 * tig] =
            h2pack(os[dt][0] * f0 + orl[dt][0], os[dt][1] * f0 + orl[dt][1]);
        *(u32*)&crow8[dt * 8 + 2 * tig] =
            h2pack(os[dt][2] * f1 + orl[dt][2], os[dt][3] * f1 + orl[dt][3]);
    }
#undef ATT_LOAD
}

// ---------------------------------------------------------------------------
extern "C" void kernel_launch(void* const* d_in, const int* in_sizes, int n_in,
                              void* d_out, int out_size)
{
    const float* hs   = (const float*)d_in[0];
    const float* Wq   = (const float*)d_in[1];
    const float* bq   = (const float*)d_in[2];
    const float* Wk   = (const float*)d_in[3];
    const float* bk   = (const float*)d_in[4];
    const float* Wv   = (const float*)d_in[5];
    const float* bv   = (const float*)d_in[6];
    const float* Wo   = (const float*)d_in[7];
    const float* bo   = (const float*)d_in[8];
    const float* wmix = (const float*)d_in[9];
    float* out = (float*)d_out;

    u16 *q, *k, *v, *c, *x, *wbuf;
    cudaGetSymbolAddress((void**)&q, g_Q);
    cudaGetSymbolAddress((void**)&k, g_K);
    cudaGetSymbolAddress((void**)&v, g_V);
    cudaGetSymbolAddress((void**)&c, g_C);
    cudaGetSymbolAddress((void**)&x, g_X);
    cudaGetSymbolAddress((void**)&wbuf, g_W);

    to_half_pre<<<2048, 256>>>(hs, Wq, Wk, Wv, Wo, x, wbuf);

    cudaFuncSetAttribute(gemm_qkv_h, cudaFuncAttributeMaxDynamicSharedMemorySize, GEMM_SM);
    gemm_qkv_h<<<dim3(D_ / 128, M_TOT / 128, 3), 256, GEMM_SM>>>(
        x, wbuf, bq, bk, bv, q, k, v);

    cudaFuncSetAttribute(attn_h, cudaFuncAttributeMaxDynamicSharedMemorySize, ATT_SM);
    attn_h<<<dim3(S_ / 128, H_, B_), 256, ATT_SM>>>(q, k, v, wmix, c);

    cudaFuncSetAttribute(gemm_out_h, cudaFuncAttributeMaxDynamicSharedMemorySize, GEMM_SM);
    gemm_out_h<<<dim3(D_ / 128, M_TOT / 128), 256, GEMM_SM>>>(
        c, wbuf + 3 * (size_t)DD, bo, out);
}

// round 8
// speedup vs baseline: 7.4983x; 1.0415x over previous
#include <cuda_runtime.h>
#include <cuda_fp16.h>
#include <math.h>
#include <stdint.h>

#define B_ 4
#define S_ 2048
#define D_ 768
#define H_ 12
#define DH_ 64
#define M_TOT (B_ * S_)          // 8192
#define NELEM (M_TOT * D_)       // 6291456
#define DD (D_ * D_)             // 589824

typedef unsigned short u16;
typedef unsigned int u32;

__device__ u16 g_Q[NELEM];
__device__ u16 g_K[NELEM];
__device__ u16 g_V[NELEM];
__device__ u16 g_C[NELEM];
__device__ u16 g_X[NELEM];
__device__ u16 g_W[4 * DD];

// ---------------------------------------------------------------------------
__device__ __forceinline__ u32 h2pack(float lo, float hi) {
    u32 r;
    asm("cvt.rn.f16x2.f32 %0, %1, %2;" : "=r"(r) : "f"(hi), "f"(lo));
    return r;
}

__device__ __forceinline__ void mma16(float* c, u32 a0, u32 a1, u32 a2, u32 a3,
                                      u32 b0, u32 b1) {
    asm volatile(
        "mma.sync.aligned.m16n8k16.row.col.f32.f16.f16.f32 "
        "{%0,%1,%2,%3},{%4,%5,%6,%7},{%8,%9},{%0,%1,%2,%3};\n"
        : "+f"(c[0]), "+f"(c[1]), "+f"(c[2]), "+f"(c[3])
        : "r"(a0), "r"(a1), "r"(a2), "r"(a3), "r"(b0), "r"(b1));
}

__device__ __forceinline__ void ldsm4(u32& r0, u32& r1, u32& r2, u32& r3, u32 addr) {
    asm volatile("ldmatrix.sync.aligned.m8n8.x4.shared.b16 {%0,%1,%2,%3}, [%4];"
                 : "=r"(r0), "=r"(r1), "=r"(r2), "=r"(r3) : "r"(addr));
}

__device__ __forceinline__ void ldsm4t(u32& r0, u32& r1, u32& r2, u32& r3, u32 addr) {
    asm volatile("ldmatrix.sync.aligned.m8n8.x4.trans.shared.b16 {%0,%1,%2,%3}, [%4];"
                 : "=r"(r0), "=r"(r1), "=r"(r2), "=r"(r3) : "r"(addr));
}

__device__ __forceinline__ void cp16(unsigned dst, const void* src) {
    asm volatile("cp.async.cg.shared.global [%0], [%1], 16;" :: "r"(dst), "l"(src));
}
#define CP_COMMIT() asm volatile("cp.async.commit_group;")
#define CP_WAIT(N) asm volatile("cp.async.wait_group %0;" :: "n"(N))

__device__ __forceinline__ unsigned smem_u32(const void* p) {
    unsigned a;
    asm("{ .reg .u64 t; cvta.to.shared.u64 t, %1; cvt.u32.u64 %0, t; }" : "=r"(a) : "l"(p));
    return a;
}

// ---------------------------------------------------------------------------
// Prepass: RN-round hidden_states and 4 weights to fp16.
// ---------------------------------------------------------------------------
__global__ void to_half_pre(const float* __restrict__ hs,
                            const float* __restrict__ Wq, const float* __restrict__ Wk,
                            const float* __restrict__ Wv, const float* __restrict__ Wo,
                            u16* __restrict__ X, u16* __restrict__ W)
{
    const int i = blockIdx.x * blockDim.x + threadIdx.x;
    const int stride = gridDim.x * blockDim.x;
    for (int j = i; j < NELEM / 4; j += stride) {
        float4 v = ((const float4*)hs)[j];
        uint2 o = {h2pack(v.x, v.y), h2pack(v.z, v.w)};
        ((uint2*)X)[j] = o;
    }
    const float* src[4] = {Wq, Wk, Wv, Wo};
#pragma unroll
    for (int w = 0; w < 4; w++) {
        const float4* s = (const float4*)src[w];
        uint2* d = (uint2*)(W + (size_t)w * DD);
        for (int j = i; j < DD / 4; j += stride) {
            float4 v = s[j];
            uint2 o = {h2pack(v.x, v.y), h2pack(v.z, v.w)};
            d[j] = o;
        }
    }
}

// ---------------------------------------------------------------------------
// fp16 GEMM body, ldmatrix fragment loads.
// 128x128 tiles, BK=64, 2x4 warp grid, m16n8k16.
// ---------------------------------------------------------------------------
#define GPH 72                      // smem pitch halves (144 B)
#define GSTGH (128 * GPH)
#define GEMM_SM (GSTGH * 2 * 2 * 2) // 73728 bytes

__device__ __forceinline__ void gemm_h_body(
    const u16* __restrict__ X, const u16* __restrict__ W,
    const float* __restrict__ bi, void* __restrict__ Yp,
    int half_out, float oscale, u16* gsm)
{
    const unsigned sb = smem_u32(gsm);
    const int tid = threadIdx.x;
    const int lane = tid & 31, wid = tid >> 5;
    const int g = lane >> 2, tig = lane & 3;
    const int wy = wid >> 2, wx = wid & 3;
    const int m0 = blockIdx.y * 128, n0 = blockIdx.x * 128;

#define GH_LOAD(s_) do {                                                        \
        int st_ = (s_) & 1;                                                     \
        unsigned ab_ = sb + st_ * (2 * GSTGH) * 2;                              \
        unsigned bb_ = ab_ + GSTGH * 2;                                         \
        _Pragma("unroll")                                                       \
        for (int u_ = 0; u_ < 4; u_++) {                                        \
            int ch_ = tid + u_ * 256;                                           \
            int r_ = ch_ >> 3, c_ = ch_ & 7;                                    \
            cp16(ab_ + r_ * 144 + c_ * 16,                                      \
                 X + (size_t)(m0 + r_) * D_ + (s_) * 64 + c_ * 8);              \
            cp16(bb_ + r_ * 144 + c_ * 16,                                      \
                 W + (size_t)(n0 + r_) * D_ + (s_) * 64 + c_ * 8);              \
        }                                                                       \
        CP_COMMIT();                                                            \
    } while (0)

    GH_LOAD(0);
    GH_LOAD(1);

    float acc[4][4][4] = {};
    const int NSLAB = D_ / 64;   // 12

    // ldmatrix lane-address components (bytes)
    const unsigned a_lrow = (lane & 15) * 144 + (lane >> 4) * 16;
    const unsigned b_lrow = (lane & 7) * 144 + (lane >> 3) * 16;

    for (int s = 0; s < NSLAB; s++) {
        if (s < NSLAB - 1) { CP_WAIT(1); } else { CP_WAIT(0); }
        __syncthreads();

        const unsigned ab = sb + (s & 1) * (2 * GSTGH) * 2;
        const unsigned bb = ab + GSTGH * 2;
        const unsigned abase = ab + (wy * 64) * 144 + a_lrow;
        const unsigned bbase = bb + (wx * 32) * 144 + b_lrow;

#pragma unroll
        for (int ksp = 0; ksp < 2; ksp++) {
            u32 b[4][4];
#pragma unroll
            for (int nt = 0; nt < 4; nt++)
                ldsm4(b[nt][0], b[nt][1], b[nt][2], b[nt][3],
                      bbase + nt * 8 * 144 + ksp * 64);
#pragma unroll
            for (int kh = 0; kh < 2; kh++) {
                const int ks = 2 * ksp + kh;
                u32 a[4][4];
#pragma unroll
                for (int mt = 0; mt < 4; mt++)
                    ldsm4(a[mt][0], a[mt][1], a[mt][2], a[mt][3],
                          abase + mt * 16 * 144 + ks * 32);
#pragma unroll
                for (int mt = 0; mt < 4; mt++)
#pragma unroll
                    for (int nt = 0; nt < 4; nt++)
                        mma16(acc[mt][nt], a[mt][0], a[mt][1], a[mt][2], a[mt][3],
                              b[nt][2 * kh], b[nt][2 * kh + 1]);
            }
        }
        __syncthreads();
        if (s + 2 < NSLAB) GH_LOAD(s + 2);
    }

#pragma unroll
    for (int nt = 0; nt < 4; nt++) {
        int c = n0 + wx * 32 + nt * 8 + 2 * tig;
        float b0v = bi[c], b1v = bi[c + 1];
#pragma unroll
        for (int mt = 0; mt < 4; mt++) {
            int r = m0 + wy * 64 + mt * 16 + g;
            float o0 = acc[mt][nt][0] + b0v;
            float o1 = acc[mt][nt][1] + b1v;
            float o2 = acc[mt][nt][2] + b0v;
            float o3 = acc[mt][nt][3] + b1v;
            if (half_out) {
                u16* Yh = (u16*)Yp;
                *(u32*)&Yh[(size_t)r * D_ + c] = h2pack(o0 * oscale, o1 * oscale);
                *(u32*)&Yh[(size_t)(r + 8) * D_ + c] = h2pack(o2 * oscale, o3 * oscale);
            } else {
                float* Yf = (float*)Yp;
                float2 q0 = {o0, o1}, q1 = {o2, o3};
                *(float2*)&Yf[(size_t)r * D_ + c] = q0;
                *(float2*)&Yf[(size_t)(r + 8) * D_ + c] = q1;
            }
        }
    }
#undef GH_LOAD
}

__global__ __launch_bounds__(256, 2) void gemm_qkv_h(
    const u16* __restrict__ X,
    const u16* __restrict__ Wh, const float* __restrict__ bq,
    const float* __restrict__ bk, const float* __restrict__ bv,
    u16* __restrict__ Yq, u16* __restrict__ Yk, u16* __restrict__ Yv)
{
    extern __shared__ u16 gsm[];
    const u16* W; const float* bi; u16* Y; float sc;
    if (blockIdx.z == 0)      { W = Wh;          bi = bq; Y = Yq; sc = 0.125f; }
    else if (blockIdx.z == 1) { W = Wh + DD;     bi = bk; Y = Yk; sc = 1.0f; }
    else                      { W = Wh + 2 * DD; bi = bv; Y = Yv; sc = 1.0f; }
    gemm_h_body(X, W, bi, Y, 1, sc, gsm);
}

__global__ __launch_bounds__(256, 2) void gemm_out_h(
    const u16* __restrict__ X, const u16* __restrict__ Wh,
    const float* __restrict__ bo, float* __restrict__ Y)
{
    extern __shared__ u16 gsm[];
    gemm_h_body(X, Wh, bo, Y, 0, 1.0f, gsm);
}

// ---------------------------------------------------------------------------
// Attention fp16 with ldmatrix K/V fragment loads.
// ---------------------------------------------------------------------------
#define KPH 72
#define KBUFB (64 * 144)            // 9216 B per tile buffer
#define OFF_VB (2 * KBUFB)
#define ATT_SM (OFF_VB + 2 * KBUFB) // 36864 B

__global__ __launch_bounds__(256, 2) void attn_h(
    const u16* __restrict__ Q, const u16* __restrict__ K,
    const u16* __restrict__ V, const float* __restrict__ wmix,
    u16* __restrict__ C)
{
    extern __shared__ u16 sm[];
    const unsigned sbase = smem_u32(sm);

    const int tid = threadIdx.x;
    const int lane = tid & 31, w = tid >> 5;
    const int g = lane >> 2, tig = lane & 3;
    const int s0 = blockIdx.x * 128;
    const int h = blockIdx.y;
    const int b = blockIdx.z;
    const size_t base = (size_t)b * S_ * D_ + (size_t)h * DH_;

    const u16* kgb = K + base;
    const u16* vgb = V + base;

    const int lrow = tid >> 3;
    const int lseg = tid & 7;

#define ATT_LOAD(kt_, sk_, sv_) do {                                            \
        const u16* kg_ = kgb + (size_t)(kt_) * 64 * D_;                         \
        const u16* vg_ = vgb + (size_t)(kt_) * 64 * D_;                         \
        _Pragma("unroll")                                                       \
        for (int u_ = 0; u_ < 2; u_++) {                                        \
            int row_ = lrow + u_ * 32;                                          \
            cp16((sk_) + row_ * 144 + lseg * 16, kg_ + (size_t)row_ * D_ + lseg * 8); \
            cp16((sv_) + row_ * 144 + lseg * 16, vg_ + (size_t)row_ * D_ + lseg * 8); \
        }                                                                       \
        CP_COMMIT();                                                            \
    } while (0)

    ATT_LOAD(0, sbase, sbase + OFF_VB);

    // Persistent Q fragments
    u32 qA[4][4];
    {
        const u16* qp = Q + base + (size_t)(s0 + w * 16 + g) * D_;
        const u16* qp8 = qp + 8 * D_;
#pragma unroll
        for (int ks = 0; ks < 4; ks++) {
            qA[ks][0] = *(const u32*)(qp + ks * 16 + 2 * tig);
            qA[ks][1] = *(const u32*)(qp8 + ks * 16 + 2 * tig);
            qA[ks][2] = *(const u32*)(qp + ks * 16 + 8 + 2 * tig);
            qA[ks][3] = *(const u32*)(qp8 + ks * 16 + 8 + 2 * tig);
        }
    }

    float e0 = __expf(wmix[0]), e1 = __expf(wmix[1]);
    float inv = 1.0f / (e0 + e1);
    const float mix0 = e0 * inv, mix1 = e1 * inv;

    float os[8][4] = {};
    float orl[8][4] = {};
    float lsum0 = 0.f, lsum1 = 0.f;

    // ldmatrix lane-address components (bytes)
    const unsigned k_lrow = (lane & 7) * 144 + (lane >> 3) * 16;
    const unsigned v_lrow = (lane & 15) * 144 + (lane >> 4) * 16;

    for (int kt = 0; kt < 32; kt++) {
        if (kt) __syncthreads();
        if (kt < 31) {
            unsigned sk = sbase + ((kt + 1) & 1) * KBUFB;
            unsigned sv = sbase + OFF_VB + ((kt + 1) & 1) * KBUFB;
            ATT_LOAD(kt + 1, sk, sv);
            CP_WAIT(1);
        } else {
            CP_WAIT(0);
        }
        __syncthreads();

        const unsigned skb = sbase + (kt & 1) * KBUFB;
        const unsigned svb = sbase + OFF_VB + (kt & 1) * KBUFB;

#pragma unroll
        for (int kvg = 0; kvg < 4; kvg++) {
            // --- QK via ldmatrix.x4 K-fragments ---
            float sce[4] = {0.f, 0.f, 0.f, 0.f};
            float sco[4] = {0.f, 0.f, 0.f, 0.f};
            const unsigned kbb = skb + (kvg * 16) * 144 + k_lrow;
#pragma unroll
            for (int ksp = 0; ksp < 2; ksp++) {
                u32 be0, be1, be2, be3, bo0, bo1, bo2, bo3;
                ldsm4(be0, be1, be2, be3, kbb + ksp * 64);
                ldsm4(bo0, bo1, bo2, bo3, kbb + 8 * 144 + ksp * 64);
                const int ks = 2 * ksp;
                mma16(sce, qA[ks][0], qA[ks][1], qA[ks][2], qA[ks][3], be0, be1);
                mma16(sce, qA[ks + 1][0], qA[ks + 1][1], qA[ks + 1][2], qA[ks + 1][3], be2, be3);
                mma16(sco, qA[ks][0], qA[ks][1], qA[ks][2], qA[ks][3], bo0, bo1);
                mma16(sco, qA[ks + 1][0], qA[ks + 1][1], qA[ks + 1][2], qA[ks + 1][3], bo2, bo3);
            }

            // --- exp / relu^2, pack PV A-frags ---
            float pe_e0 = __expf(sce[0]), pe_e1 = __expf(sce[1]);
            float pe_e2 = __expf(sce[2]), pe_e3 = __expf(sce[3]);
            float pe_o0 = __expf(sco[0]), pe_o1 = __expf(sco[1]);
            float pe_o2 = __expf(sco[2]), pe_o3 = __expf(sco[3]);
            lsum0 += pe_e0 + pe_e1 + pe_o0 + pe_o1;
            lsum1 += pe_e2 + pe_e3 + pe_o2 + pe_o3;

            float pq_e0 = sce[0] > 0.f ? mix1 * sce[0] * sce[0] : 0.f;
            float pq_e1 = sce[1] > 0.f ? mix1 * sce[1] * sce[1] : 0.f;
            float pq_e2 = sce[2] > 0.f ? mix1 * sce[2] * sce[2] : 0.f;
            float pq_e3 = sce[3] > 0.f ? mix1 * sce[3] * sce[3] : 0.f;
            float pq_o0 = sco[0] > 0.f ? mix1 * sco[0] * sco[0] : 0.f;
            float pq_o1 = sco[1] > 0.f ? mix1 * sco[1] * sco[1] : 0.f;
            float pq_o2 = sco[2] > 0.f ? mix1 * sco[2] * sco[2] : 0.f;
            float pq_o3 = sco[3] > 0.f ? mix1 * sco[3] * sco[3] : 0.f;

            u32 ape0 = h2pack(pe_e0, pe_e1);
            u32 ape1 = h2pack(pe_e2, pe_e3);
            u32 ape2 = h2pack(pe_o0, pe_o1);
            u32 ape3 = h2pack(pe_o2, pe_o3);
            u32 apq0 = h2pack(pq_e0, pq_e1);
            u32 apq1 = h2pack(pq_e2, pq_e3);
            u32 apq2 = h2pack(pq_o0, pq_o1);
            u32 apq3 = h2pack(pq_o2, pq_o3);

            // --- PV via ldmatrix.x4.trans V-fragments ---
            const unsigned vbb = svb + (kvg * 16) * 144 + v_lrow;
#pragma unroll
            for (int dtp = 0; dtp < 4; dtp++) {
                u32 v0, v1, v2, v3;
                ldsm4t(v0, v1, v2, v3, vbb + dtp * 32);
                mma16(os[2 * dtp], ape0, ape1, ape2, ape3, v0, v1);
                mma16(orl[2 * dtp], apq0, apq1, apq2, apq3, v0, v1);
                mma16(os[2 * dtp + 1], ape0, ape1, ape2, ape3, v2, v3);
                mma16(orl[2 * dtp + 1], apq0, apq1, apq2, apq3, v2, v3);
            }
        }
    }

    lsum0 += __shfl_xor_sync(0xffffffffu, lsum0, 1);
    lsum0 += __shfl_xor_sync(0xffffffffu, lsum0, 2);
    lsum1 += __shfl_xor_sync(0xffffffffu, lsum1, 1);
    lsum1 += __shfl_xor_sync(0xffffffffu, lsum1, 2);

    float f0 = mix0 / lsum0;
    float f1 = mix0 / lsum1;

    u16* crow = C + base + (size_t)(s0 + w * 16 + g) * D_;
    u16* crow8 = crow + 8 * D_;
#pragma unroll
    for (int dt = 0; dt < 8; dt++) {
        *(u32*)&crow[dt * 8 + 2 * tig] =
            h2pack(os[dt][0] * f0 + orl[dt][0], os[dt][1] * f0 + orl[dt][1]);
        *(u32*)&crow8[dt * 8 + 2 * tig] =
            h2pack(os[dt][2] * f1 + orl[dt][2], os[dt][3] * f1 + orl[dt][3]);
    }
#undef ATT_LOAD
}

// ---------------------------------------------------------------------------
extern "C" void kernel_launch(void* const* d_in, const int* in_sizes, int n_in,
                              void* d_out, int out_size)
{
    const float* hs   = (const float*)d_in[0];
    const float* Wq   = (const float*)d_in[1];
    const float* bq   = (const float*)d_in[2];
    const float* Wk   = (const float*)d_in[3];
    const float* bk   = (const float*)d_in[4];
    const float* Wv   = (const float*)d_in[5];
    const float* bv   = (const float*)d_in[6];
    const float* Wo   = (const float*)d_in[7];
    const float* bo   = (const float*)d_in[8];
    const float* wmix = (const float*)d_in[9];
    float* out = (float*)d_out;

    u16 *q, *k, *v, *c, *x, *wbuf;
    cudaGetSymbolAddress((void**)&q, g_Q);
    cudaGetSymbolAddress((void**)&k, g_K);
    cudaGetSymbolAddress((void**)&v, g_V);
    cudaGetSymbolAddress((void**)&c, g_C);
    cudaGetSymbolAddress((void**)&x, g_X);
    cudaGetSymbolAddress((void**)&wbuf, g_W);

    to_half_pre<<<2048, 256>>>(hs, Wq, Wk, Wv, Wo, x, wbuf);

    cudaFuncSetAttribute(gemm_qkv_h, cudaFuncAttributeMaxDynamicSharedMemorySize, GEMM_SM);
    gemm_qkv_h<<<dim3(D_ / 128, M_TOT / 128, 3), 256, GEMM_SM>>>(
        x, wbuf, bq, bk, bv, q, k, v);

    cudaFuncSetAttribute(attn_h, cudaFuncAttributeMaxDynamicSharedMemorySize, ATT_SM);
    attn_h<<<dim3(S_ / 128, H_, B_), 256, ATT_SM>>>(q, k, v, wmix, c);

    cudaFuncSetAttribute(gemm_out_h, cudaFuncAttributeMaxDynamicSharedMemorySize, GEMM_SM);
    gemm_out_h<<<dim3(D_ / 128, M_TOT / 128), 256, GEMM_SM>>>(
        c, wbuf + 3 * (size_t)DD, bo, out);
}

// round 9
// speedup vs baseline: 8.1294x; 1.0842x over previous
#include <cuda_runtime.h>
#include <cuda_fp16.h>
#include <math.h>
#include <stdint.h>

#define B_ 4
#define S_ 2048
#define D_ 768
#define H_ 12
#define DH_ 64
#define M_TOT (B_ * S_)          // 8192
#define NELEM (M_TOT * D_)       // 6291456
#define DD (D_ * D_)             // 589824

typedef unsigned short u16;
typedef unsigned int u32;

__device__ u16 g_Q[NELEM];
__device__ u16 g_K[NELEM];
__device__ u16 g_V[NELEM];
__device__ u16 g_C[NELEM];
__device__ u16 g_X[NELEM];
__device__ u16 g_W[4 * DD];

// Q prescale: 1/8 (score scale) * log2(e) (exp -> ex2 domain)
#define QSCALE 0.18033688011112042f
// ln2^2: converts (s*log2e)^2 back to s^2 in the relu^2 branch
#define LN2SQ 0.4804530139182014f

// ---------------------------------------------------------------------------
__device__ __forceinline__ u32 h2pack(float lo, float hi) {
    u32 r;
    asm("cvt.rn.f16x2.f32 %0, %1, %2;" : "=r"(r) : "f"(hi), "f"(lo));
    return r;
}

__device__ __forceinline__ u32 ex2h2(u32 x) {
    u32 r;
    asm("ex2.approx.f16x2 %0, %1;" : "=r"(r) : "r"(x));
    return r;
}

__device__ __forceinline__ void mma16(float* c, u32 a0, u32 a1, u32 a2, u32 a3,
                                      u32 b0, u32 b1) {
    asm volatile(
        "mma.sync.aligned.m16n8k16.row.col.f32.f16.f16.f32 "
        "{%0,%1,%2,%3},{%4,%5,%6,%7},{%8,%9},{%0,%1,%2,%3};\n"
        : "+f"(c[0]), "+f"(c[1]), "+f"(c[2]), "+f"(c[3])
        : "r"(a0), "r"(a1), "r"(a2), "r"(a3), "r"(b0), "r"(b1));
}

__device__ __forceinline__ void ldsm4(u32& r0, u32& r1, u32& r2, u32& r3, u32 addr) {
    asm volatile("ldmatrix.sync.aligned.m8n8.x4.shared.b16 {%0,%1,%2,%3}, [%4];"
                 : "=r"(r0), "=r"(r1), "=r"(r2), "=r"(r3) : "r"(addr));
}

__device__ __forceinline__ void ldsm4t(u32& r0, u32& r1, u32& r2, u32& r3, u32 addr) {
    asm volatile("ldmatrix.sync.aligned.m8n8.x4.trans.shared.b16 {%0,%1,%2,%3}, [%4];"
                 : "=r"(r0), "=r"(r1), "=r"(r2), "=r"(r3) : "r"(addr));
}

__device__ __forceinline__ void cp16(unsigned dst, const void* src) {
    asm volatile("cp.async.cg.shared.global [%0], [%1], 16;" :: "r"(dst), "l"(src));
}
#define CP_COMMIT() asm volatile("cp.async.commit_group;")
#define CP_WAIT(N) asm volatile("cp.async.wait_group %0;" :: "n"(N))

__device__ __forceinline__ unsigned smem_u32(const void* p) {
    unsigned a;
    asm("{ .reg .u64 t; cvta.to.shared.u64 t, %1; cvt.u32.u64 %0, t; }" : "=r"(a) : "l"(p));
    return a;
}

// ---------------------------------------------------------------------------
// Prepass: RN-round hidden_states and 4 weights to fp16.
// ---------------------------------------------------------------------------
__global__ void to_half_pre(const float* __restrict__ hs,
                            const float* __restrict__ Wq, const float* __restrict__ Wk,
                            const float* __restrict__ Wv, const float* __restrict__ Wo,
                            u16* __restrict__ X, u16* __restrict__ W)
{
    const int i = blockIdx.x * blockDim.x + threadIdx.x;
    const int stride = gridDim.x * blockDim.x;
    for (int j = i; j < NELEM / 4; j += stride) {
        float4 v = ((const float4*)hs)[j];
        uint2 o = {h2pack(v.x, v.y), h2pack(v.z, v.w)};
        ((uint2*)X)[j] = o;
    }
    const float* src[4] = {Wq, Wk, Wv, Wo};
#pragma unroll
    for (int w = 0; w < 4; w++) {
        const float4* s = (const float4*)src[w];
        uint2* d = (uint2*)(W + (size_t)w * DD);
        for (int j = i; j < DD / 4; j += stride) {
            float4 v = s[j];
            uint2 o = {h2pack(v.x, v.y), h2pack(v.z, v.w)};
            d[j] = o;
        }
    }
}

// ---------------------------------------------------------------------------
// fp16 GEMM body (unchanged from R8): 128x128 tiles, BK=64, ldmatrix frags.
// ---------------------------------------------------------------------------
#define GPH 72
#define GSTGH (128 * GPH)
#define GEMM_SM (GSTGH * 2 * 2 * 2) // 73728 bytes

__device__ __forceinline__ void gemm_h_body(
    const u16* __restrict__ X, const u16* __restrict__ W,
    const float* __restrict__ bi, void* __restrict__ Yp,
    int half_out, float oscale, u16* gsm)
{
    const unsigned sb = smem_u32(gsm);
    const int tid = threadIdx.x;
    const int lane = tid & 31, wid = tid >> 5;
    const int g = lane >> 2, tig = lane & 3;
    const int wy = wid >> 2, wx = wid & 3;
    const int m0 = blockIdx.y * 128, n0 = blockIdx.x * 128;

#define GH_LOAD(s_) do {                                                        \
        int st_ = (s_) & 1;                                                     \
        unsigned ab_ = sb + st_ * (2 * GSTGH) * 2;                              \
        unsigned bb_ = ab_ + GSTGH * 2;                                         \
        _Pragma("unroll")                                                       \
        for (int u_ = 0; u_ < 4; u_++) {                                        \
            int ch_ = tid + u_ * 256;                                           \
            int r_ = ch_ >> 3, c_ = ch_ & 7;                                    \
            cp16(ab_ + r_ * 144 + c_ * 16,                                      \
                 X + (size_t)(m0 + r_) * D_ + (s_) * 64 + c_ * 8);              \
            cp16(bb_ + r_ * 144 + c_ * 16,                                      \
                 W + (size_t)(n0 + r_) * D_ + (s_) * 64 + c_ * 8);              \
        }                                                                       \
        CP_COMMIT();                                                            \
    } while (0)

    GH_LOAD(0);
    GH_LOAD(1);

    float acc[4][4][4] = {};
    const int NSLAB = D_ / 64;   // 12

    const unsigned a_lrow = (lane & 15) * 144 + (lane >> 4) * 16;
    const unsigned b_lrow = (lane & 7) * 144 + (lane >> 3) * 16;

    for (int s = 0; s < NSLAB; s++) {
        if (s < NSLAB - 1) { CP_WAIT(1); } else { CP_WAIT(0); }
        __syncthreads();

        const unsigned ab = sb + (s & 1) * (2 * GSTGH) * 2;
        const unsigned bb = ab + GSTGH * 2;
        const unsigned abase = ab + (wy * 64) * 144 + a_lrow;
        const unsigned bbase = bb + (wx * 32) * 144 + b_lrow;

#pragma unroll
        for (int ksp = 0; ksp < 2; ksp++) {
            u32 b[4][4];
#pragma unroll
            for (int nt = 0; nt < 4; nt++)
                ldsm4(b[nt][0], b[nt][1], b[nt][2], b[nt][3],
                      bbase + nt * 8 * 144 + ksp * 64);
#pragma unroll
            for (int kh = 0; kh < 2; kh++) {
                const int ks = 2 * ksp + kh;
                u32 a[4][4];
#pragma unroll
                for (int mt = 0; mt < 4; mt++)
                    ldsm4(a[mt][0], a[mt][1], a[mt][2], a[mt][3],
                          abase + mt * 16 * 144 + ks * 32);
#pragma unroll
                for (int mt = 0; mt < 4; mt++)
#pragma unroll
                    for (int nt = 0; nt < 4; nt++)
                        mma16(acc[mt][nt], a[mt][0], a[mt][1], a[mt][2], a[mt][3],
                              b[nt][2 * kh], b[nt][2 * kh + 1]);
            }
        }
        __syncthreads();
        if (s + 2 < NSLAB) GH_LOAD(s + 2);
    }

#pragma unroll
    for (int nt = 0; nt < 4; nt++) {
        int c = n0 + wx * 32 + nt * 8 + 2 * tig;
        float b0v = bi[c], b1v = bi[c + 1];
#pragma unroll
        for (int mt = 0; mt < 4; mt++) {
            int r = m0 + wy * 64 + mt * 16 + g;
            float o0 = acc[mt][nt][0] + b0v;
            float o1 = acc[mt][nt][1] + b1v;
            float o2 = acc[mt][nt][2] + b0v;
            float o3 = acc[mt][nt][3] + b1v;
            if (half_out) {
                u16* Yh = (u16*)Yp;
                *(u32*)&Yh[(size_t)r * D_ + c] = h2pack(o0 * oscale, o1 * oscale);
                *(u32*)&Yh[(size_t)(r + 8) * D_ + c] = h2pack(o2 * oscale, o3 * oscale);
            } else {
                float* Yf = (float*)Yp;
                float2 q0 = {o0, o1}, q1 = {o2, o3};
                *(float2*)&Yf[(size_t)r * D_ + c] = q0;
                *(float2*)&Yf[(size_t)(r + 8) * D_ + c] = q1;
            }
        }
    }
#undef GH_LOAD
}

__global__ __launch_bounds__(256, 2) void gemm_qkv_h(
    const u16* __restrict__ X,
    const u16* __restrict__ Wh, const float* __restrict__ bq,
    const float* __restrict__ bk, const float* __restrict__ bv,
    u16* __restrict__ Yq, u16* __restrict__ Yk, u16* __restrict__ Yv)
{
    extern __shared__ u16 gsm[];
    const u16* W; const float* bi; u16* Y; float sc;
    if (blockIdx.z == 0)      { W = Wh;          bi = bq; Y = Yq; sc = QSCALE; }
    else if (blockIdx.z == 1) { W = Wh + DD;     bi = bk; Y = Yk; sc = 1.0f; }
    else                      { W = Wh + 2 * DD; bi = bv; Y = Yv; sc = 1.0f; }
    gemm_h_body(X, W, bi, Y, 1, sc, gsm);
}

__global__ __launch_bounds__(256, 2) void gemm_out_h(
    const u16* __restrict__ X, const u16* __restrict__ Wh,
    const float* __restrict__ bo, float* __restrict__ Y)
{
    extern __shared__ u16 gsm[];
    gemm_h_body(X, Wh, bo, Y, 0, 1.0f, gsm);
}

// ---------------------------------------------------------------------------
// Attention fp16 v3: 128-row kv tiles, ex2.f16x2 exp, lsum via ones-column MMA.
// S arrives log2e-scaled (Q prescale). pe = ex2(s'), pq = max(s',0)^2 (scaled
// back by mix1*ln2^2 in epilogue). Row sums accumulate in an extra MMA whose
// B is ones in column 0 only.
// ---------------------------------------------------------------------------
#define KPH 72
#define KTILE 128
#define KBUFB (KTILE * 144)          // 18432 B
#define OFF_VB (2 * KBUFB)           // 36864
#define ATT_SM (OFF_VB + 2 * KBUFB)  // 73728 B
#define NKT (S_ / KTILE)             // 16

__global__ __launch_bounds__(256, 2) void attn_h(
    const u16* __restrict__ Q, const u16* __restrict__ K,
    const u16* __restrict__ V, const float* __restrict__ wmix,
    u16* __restrict__ C)
{
    extern __shared__ u16 sm[];
    const unsigned sbase = smem_u32(sm);

    const int tid = threadIdx.x;
    const int lane = tid & 31, w = tid >> 5;
    const int g = lane >> 2, tig = lane & 3;
    const int s0 = blockIdx.x * 128;
    const int h = blockIdx.y;
    const int b = blockIdx.z;
    const size_t base = (size_t)b * S_ * D_ + (size_t)h * DH_;

    const u16* kgb = K + base;
    const u16* vgb = V + base;

    const int lrow = tid >> 3;       // 0..31
    const int lseg = tid & 7;

#define ATT_LOAD(kt_, sk_, sv_) do {                                            \
        const u16* kg_ = kgb + (size_t)(kt_) * KTILE * D_;                      \
        const u16* vg_ = vgb + (size_t)(kt_) * KTILE * D_;                      \
        _Pragma("unroll")                                                       \
        for (int u_ = 0; u_ < 4; u_++) {                                        \
            int row_ = lrow + u_ * 32;                                          \
            cp16((sk_) + row_ * 144 + lseg * 16, kg_ + (size_t)row_ * D_ + lseg * 8); \
            cp16((sv_) + row_ * 144 + lseg * 16, vg_ + (size_t)row_ * D_ + lseg * 8); \
        }                                                                       \
        CP_COMMIT();                                                            \
    } while (0)

    ATT_LOAD(0, sbase, sbase + OFF_VB);

    // Persistent Q fragments (Q pre-scaled by 0.125*log2e)
    u32 qA[4][4];
    {
        const u16* qp = Q + base + (size_t)(s0 + w * 16 + g) * D_;
        const u16* qp8 = qp + 8 * D_;
#pragma unroll
        for (int ks = 0; ks < 4; ks++) {
            qA[ks][0] = *(const u32*)(qp + ks * 16 + 2 * tig);
            qA[ks][1] = *(const u32*)(qp8 + ks * 16 + 2 * tig);
            qA[ks][2] = *(const u32*)(qp + ks * 16 + 8 + 2 * tig);
            qA[ks][3] = *(const u32*)(qp8 + ks * 16 + 8 + 2 * tig);
        }
    }

    float e0 = __expf(wmix[0]), e1 = __expf(wmix[1]);
    float inv = 1.0f / (e0 + e1);
    const float mix0 = e0 * inv;
    const float mix1l = e1 * inv * LN2SQ;

    float os[8][4] = {};
    float orl[8][4] = {};
    float ls[4] = {};                       // row sums via ones-column MMA
    const u32 oneb = (g == 0) ? 0x3C003C00u : 0u;

    const unsigned k_lrow = (lane & 7) * 144 + (lane >> 3) * 16;
    const unsigned v_lrow = (lane & 15) * 144 + (lane >> 4) * 16;

    for (int kt = 0; kt < NKT; kt++) {
        if (kt) __syncthreads();
        if (kt < NKT - 1) {
            unsigned sk = sbase + ((kt + 1) & 1) * KBUFB;
            unsigned sv = sbase + OFF_VB + ((kt + 1) & 1) * KBUFB;
            ATT_LOAD(kt + 1, sk, sv);
            CP_WAIT(1);
        } else {
            CP_WAIT(0);
        }
        __syncthreads();

        const unsigned skb = sbase + (kt & 1) * KBUFB;
        const unsigned svb = sbase + OFF_VB + (kt & 1) * KBUFB;

#pragma unroll
        for (int kvg = 0; kvg < 8; kvg++) {
            // --- QK via ldmatrix.x4 K-fragments ---
            float sce[4] = {0.f, 0.f, 0.f, 0.f};
            float sco[4] = {0.f, 0.f, 0.f, 0.f};
            const unsigned kbb = skb + (kvg * 16) * 144 + k_lrow;
#pragma unroll
            for (int ksp = 0; ksp < 2; ksp++) {
                u32 be0, be1, be2, be3, bo0, bo1, bo2, bo3;
                ldsm4(be0, be1, be2, be3, kbb + ksp * 64);
                ldsm4(bo0, bo1, bo2, bo3, kbb + 8 * 144 + ksp * 64);
                const int ks = 2 * ksp;
                mma16(sce, qA[ks][0], qA[ks][1], qA[ks][2], qA[ks][3], be0, be1);
                mma16(sce, qA[ks + 1][0], qA[ks + 1][1], qA[ks + 1][2], qA[ks + 1][3], be2, be3);
                mma16(sco, qA[ks][0], qA[ks][1], qA[ks][2], qA[ks][3], bo0, bo1);
                mma16(sco, qA[ks + 1][0], qA[ks + 1][1], qA[ks + 1][2], qA[ks + 1][3], bo2, bo3);
            }

            // --- pe = ex2(s') packed; pq = max(s',0)^2 packed ---
            u32 ape0 = ex2h2(h2pack(sce[0], sce[1]));
            u32 ape1 = ex2h2(h2pack(sce[2], sce[3]));
            u32 ape2 = ex2h2(h2pack(sco[0], sco[1]));
            u32 ape3 = ex2h2(h2pack(sco[2], sco[3]));

            float re0 = fmaxf(sce[0], 0.f), re1 = fmaxf(sce[1], 0.f);
            float re2 = fmaxf(sce[2], 0.f), re3 = fmaxf(sce[3], 0.f);
            float ro0 = fmaxf(sco[0], 0.f), ro1 = fmaxf(sco[1], 0.f);
            float ro2 = fmaxf(sco[2], 0.f), ro3 = fmaxf(sco[3], 0.f);
            u32 apq0 = h2pack(re0 * re0, re1 * re1);
            u32 apq1 = h2pack(re2 * re2, re3 * re3);
            u32 apq2 = h2pack(ro0 * ro0, ro1 * ro1);
            u32 apq3 = h2pack(ro2 * ro2, ro3 * ro3);

            // --- row sums of pe (tensor pipe; col 0 only) ---
            mma16(ls, ape0, ape1, ape2, ape3, oneb, oneb);

            // --- PV via ldmatrix.x4.trans V-fragments ---
            const unsigned vbb = svb + (kvg * 16) * 144 + v_lrow;
#pragma unroll
            for (int dtp = 0; dtp < 4; dtp++) {
                u32 v0, v1, v2, v3;
                ldsm4t(v0, v1, v2, v3, vbb + dtp * 32);
                mma16(os[2 * dtp], ape0, ape1, ape2, ape3, v0, v1);
                mma16(orl[2 * dtp], apq0, apq1, apq2, apq3, v0, v1);
                mma16(os[2 * dtp + 1], ape0, ape1, ape2, ape3, v2, v3);
                mma16(orl[2 * dtp + 1], apq0, apq1, apq2, apq3, v2, v3);
            }
        }
    }

    // Row sums live in col 0 (tig==0 lanes); broadcast within each quad.
    float l0 = __shfl_sync(0xffffffffu, ls[0], lane & 28);
    float l1 = __shfl_sync(0xffffffffu, ls[2], lane & 28);
    float f0 = mix0 / l0;
    float f1 = mix0 / l1;

    u16* crow = C + base + (size_t)(s0 + w * 16 + g) * D_;
    u16* crow8 = crow + 8 * D_;
#pragma unroll
    for (int dt = 0; dt < 8; dt++) {
        *(u32*)&crow[dt * 8 + 2 * tig] =
            h2pack(os[dt][0] * f0 + orl[dt][0] * mix1l,
                   os[dt][1] * f0 + orl[dt][1] * mix1l);
        *(u32*)&crow8[dt * 8 + 2 * tig] =
            h2pack(os[dt][2] * f1 + orl[dt][2] * mix1l,
                   os[dt][3] * f1 + orl[dt][3] * mix1l);
    }
#undef ATT_LOAD
}

// ---------------------------------------------------------------------------
extern "C" void kernel_launch(void* const* d_in, const int* in_sizes, int n_in,
                              void* d_out, int out_size)
{
    const float* hs   = (const float*)d_in[0];
    const float* Wq   = (const float*)d_in[1];
    const float* bq   = (const float*)d_in[2];
    const float* Wk   = (const float*)d_in[3];
    const float* bk   = (const float*)d_in[4];
    const float* Wv   = (const float*)d_in[5];
    const float* bv   = (const float*)d_in[6];
    const float* Wo   = (const float*)d_in[7];
    const float* bo   = (const float*)d_in[8];
    const float* wmix = (const float*)d_in[9];
    float* out = (float*)d_out;

    u16 *q, *k, *v, *c, *x, *wbuf;
    cudaGetSymbolAddress((void**)&q, g_Q);
    cudaGetSymbolAddress((void**)&k, g_K);
    cudaGetSymbolAddress((void**)&v, g_V);
    cudaGetSymbolAddress((void**)&c, g_C);
    cudaGetSymbolAddress((void**)&x, g_X);
    cudaGetSymbolAddress((void**)&wbuf, g_W);

    to_half_pre<<<2048, 256>>>(hs, Wq, Wk, Wv, Wo, x, wbuf);

    cudaFuncSetAttribute(gemm_qkv_h, cudaFuncAttributeMaxDynamicSharedMemorySize, GEMM_SM);
    gemm_qkv_h<<<dim3(D_ / 128, M_TOT / 128, 3), 256, GEMM_SM>>>(
        x, wbuf, bq, bk, bv, q, k, v);

    cudaFuncSetAttribute(attn_h, cudaFuncAttributeMaxDynamicSharedMemorySize, ATT_SM);
    attn_h<<<dim3(S_ / 128, H_, B_), 256, ATT_SM>>>(q, k, v, wmix, c);

    cudaFuncSetAttribute(gemm_out_h, cudaFuncAttributeMaxDynamicSharedMemorySize, GEMM_SM);
    gemm_out_h<<<dim3(D_ / 128, M_TOT / 128), 256, GEMM_SM>>>(
        c, wbuf + 3 * (size_t)DD, bo, out);
}

// round 10
// speedup vs baseline: 8.1609x; 1.0039x over previous
#include <cuda_runtime.h>
#include <cuda_fp16.h>
#include <math.h>
#include <stdint.h>

#define B_ 4
#define S_ 2048
#define D_ 768
#define H_ 12
#define DH_ 64
#define M_TOT (B_ * S_)          // 8192
#define NELEM (M_TOT * D_)       // 6291456
#define DD (D_ * D_)             // 589824

typedef unsigned short u16;
typedef unsigned int u32;

__device__ u16 g_Q[NELEM];
__device__ u16 g_K[NELEM];
__device__ u16 g_V[NELEM];
__device__ u16 g_C[NELEM];
__device__ u16 g_X[NELEM];
__device__ u16 g_W[4 * DD];

// Q prescale: 1/8 (score scale) * log2(e) (exp -> ex2 domain)
#define QSCALE 0.18033688011112042f
// ln2^2: converts (s*log2e)^2 back to s^2 in the relu^2 branch
#define LN2SQ 0.4804530139182014f

// ---------------------------------------------------------------------------
__device__ __forceinline__ u32 h2pack(float lo, float hi) {
    u32 r;
    asm("cvt.rn.f16x2.f32 %0, %1, %2;" : "=r"(r) : "f"(hi), "f"(lo));
    return r;
}

__device__ __forceinline__ u32 ex2h2(u32 x) {
    u32 r;
    asm("ex2.approx.f16x2 %0, %1;" : "=r"(r) : "r"(x));
    return r;
}

__device__ __forceinline__ void mma16(float* c, u32 a0, u32 a1, u32 a2, u32 a3,
                                      u32 b0, u32 b1) {
    asm volatile(
        "mma.sync.aligned.m16n8k16.row.col.f32.f16.f16.f32 "
        "{%0,%1,%2,%3},{%4,%5,%6,%7},{%8,%9},{%0,%1,%2,%3};\n"
        : "+f"(c[0]), "+f"(c[1]), "+f"(c[2]), "+f"(c[3])
        : "r"(a0), "r"(a1), "r"(a2), "r"(a3), "r"(b0), "r"(b1));
}

__device__ __forceinline__ void ldsm4(u32& r0, u32& r1, u32& r2, u32& r3, u32 addr) {
    asm volatile("ldmatrix.sync.aligned.m8n8.x4.shared.b16 {%0,%1,%2,%3}, [%4];"
                 : "=r"(r0), "=r"(r1), "=r"(r2), "=r"(r3) : "r"(addr));
}

__device__ __forceinline__ void ldsm4t(u32& r0, u32& r1, u32& r2, u32& r3, u32 addr) {
    asm volatile("ldmatrix.sync.aligned.m8n8.x4.trans.shared.b16 {%0,%1,%2,%3}, [%4];"
                 : "=r"(r0), "=r"(r1), "=r"(r2), "=r"(r3) : "r"(addr));
}

__device__ __forceinline__ void cp16(unsigned dst, const void* src) {
    asm volatile("cp.async.cg.shared.global [%0], [%1], 16;" :: "r"(dst), "l"(src));
}
#define CP_COMMIT() asm volatile("cp.async.commit_group;")
#define CP_WAIT(N) asm volatile("cp.async.wait_group %0;" :: "n"(N))

__device__ __forceinline__ unsigned smem_u32(const void* p) {
    unsigned a;
    asm("{ .reg .u64 t; cvta.to.shared.u64 t, %1; cvt.u32.u64 %0, t; }" : "=r"(a) : "l"(p));
    return a;
}

// ---------------------------------------------------------------------------
// Prepass: RN-round hidden_states and 4 weights to fp16.
// ---------------------------------------------------------------------------
__global__ void to_half_pre(const float* __restrict__ hs,
                            const float* __restrict__ Wq, const float* __restrict__ Wk,
                            const float* __restrict__ Wv, const float* __restrict__ Wo,
                            u16* __restrict__ X, u16* __restrict__ W)
{
    const int i = blockIdx.x * blockDim.x + threadIdx.x;
    const int stride = gridDim.x * blockDim.x;
    for (int j = i; j < NELEM / 4; j += stride) {
        float4 v = ((const float4*)hs)[j];
        uint2 o = {h2pack(v.x, v.y), h2pack(v.z, v.w)};
        ((uint2*)X)[j] = o;
    }
    const float* src[4] = {Wq, Wk, Wv, Wo};
#pragma unroll
    for (int w = 0; w < 4; w++) {
        const float4* s = (const float4*)src[w];
        uint2* d = (uint2*)(W + (size_t)w * DD);
        for (int j = i; j < DD / 4; j += stride) {
            float4 v = s[j];
            uint2 o = {h2pack(v.x, v.y), h2pack(v.z, v.w)};
            d[j] = o;
        }
    }
}

// ---------------------------------------------------------------------------
// fp16 GEMM body: 128x128 tiles, BK=64, ldmatrix frags,
// 3-stage cp.async ring with ONE barrier per slab, loads issued pre-compute.
// ---------------------------------------------------------------------------
#define GPH 72
#define GSTGH (128 * GPH)
#define GSTGB (GSTGH * 2 * 2)        // bytes per stage (A+B) = 36864
#define GEMM_SM (3 * GSTGB)          // 110592 bytes

__device__ __forceinline__ void gemm_h_body(
    const u16* __restrict__ X, const u16* __restrict__ W,
    const float* __restrict__ bi, void* __restrict__ Yp,
    int half_out, float oscale, u16* gsm)
{
    const unsigned sb = smem_u32(gsm);
    const int tid = threadIdx.x;
    const int lane = tid & 31, wid = tid >> 5;
    const int g = lane >> 2, tig = lane & 3;
    const int wy = wid >> 2, wx = wid & 3;
    const int m0 = blockIdx.y * 128, n0 = blockIdx.x * 128;

#define GH_LOAD(s_) do {                                                        \
        int st_ = (s_) % 3;                                                     \
        unsigned ab_ = sb + st_ * GSTGB;                                        \
        unsigned bb_ = ab_ + GSTGH * 2;                                         \
        _Pragma("unroll")                                                       \
        for (int u_ = 0; u_ < 4; u_++) {                                        \
            int ch_ = tid + u_ * 256;                                           \
            int r_ = ch_ >> 3, c_ = ch_ & 7;                                    \
            cp16(ab_ + r_ * 144 + c_ * 16,                                      \
                 X + (size_t)(m0 + r_) * D_ + (s_) * 64 + c_ * 8);              \
            cp16(bb_ + r_ * 144 + c_ * 16,                                      \
                 W + (size_t)(n0 + r_) * D_ + (s_) * 64 + c_ * 8);              \
        }                                                                       \
        CP_COMMIT();                                                            \
    } while (0)

    GH_LOAD(0);
    GH_LOAD(1);

    float acc[4][4][4] = {};
    const int NSLAB = D_ / 64;   // 12

    const unsigned a_lrow = (lane & 15) * 144 + (lane >> 4) * 16;
    const unsigned b_lrow = (lane & 7) * 144 + (lane >> 3) * 16;

    for (int s = 0; s < NSLAB; s++) {
        if (s < NSLAB - 2) { CP_WAIT(1); } else { CP_WAIT(0); }
        __syncthreads();
        if (s + 2 < NSLAB) GH_LOAD(s + 2);

        const unsigned ab = sb + (s % 3) * GSTGB;
        const unsigned bb = ab + GSTGH * 2;
        const unsigned abase = ab + (wy * 64) * 144 + a_lrow;
        const unsigned bbase = bb + (wx * 32) * 144 + b_lrow;

#pragma unroll
        for (int ksp = 0; ksp < 2; ksp++) {
            u32 b[4][4];
#pragma unroll
            for (int nt = 0; nt < 4; nt++)
                ldsm4(b[nt][0], b[nt][1], b[nt][2], b[nt][3],
                      bbase + nt * 8 * 144 + ksp * 64);
#pragma unroll
            for (int kh = 0; kh < 2; kh++) {
                const int ks = 2 * ksp + kh;
                u32 a[4][4];
#pragma unroll
                for (int mt = 0; mt < 4; mt++)
                    ldsm4(a[mt][0], a[mt][1], a[mt][2], a[mt][3],
                          abase + mt * 16 * 144 + ks * 32);
#pragma unroll
                for (int mt = 0; mt < 4; mt++)
#pragma unroll
                    for (int nt = 0; nt < 4; nt++)
                        mma16(acc[mt][nt], a[mt][0], a[mt][1], a[mt][2], a[mt][3],
                              b[nt][2 * kh], b[nt][2 * kh + 1]);
            }
        }
    }

#pragma unroll
    for (int nt = 0; nt < 4; nt++) {
        int c = n0 + wx * 32 + nt * 8 + 2 * tig;
        float b0v = bi[c], b1v = bi[c + 1];
#pragma unroll
        for (int mt = 0; mt < 4; mt++) {
            int r = m0 + wy * 64 + mt * 16 + g;
            float o0 = acc[mt][nt][0] + b0v;
            float o1 = acc[mt][nt][1] + b1v;
            float o2 = acc[mt][nt][2] + b0v;
            float o3 = acc[mt][nt][3] + b1v;
            if (half_out) {
                u16* Yh = (u16*)Yp;
                *(u32*)&Yh[(size_t)r * D_ + c] = h2pack(o0 * oscale, o1 * oscale);
                *(u32*)&Yh[(size_t)(r + 8) * D_ + c] = h2pack(o2 * oscale, o3 * oscale);
            } else {
                float* Yf = (float*)Yp;
                float2 q0 = {o0, o1}, q1 = {o2, o3};
                *(float2*)&Yf[(size_t)r * D_ + c] = q0;
                *(float2*)&Yf[(size_t)(r + 8) * D_ + c] = q1;
            }
        }
    }
#undef GH_LOAD
}

__global__ __launch_bounds__(256, 2) void gemm_qkv_h(
    const u16* __restrict__ X,
    const u16* __restrict__ Wh, const float* __restrict__ bq,
    const float* __restrict__ bk, const float* __restrict__ bv,
    u16* __restrict__ Yq, u16* __restrict__ Yk, u16* __restrict__ Yv)
{
    extern __shared__ u16 gsm[];
    const u16* W; const float* bi; u16* Y; float sc;
    if (blockIdx.z == 0)      { W = Wh;          bi = bq; Y = Yq; sc = QSCALE; }
    else if (blockIdx.z == 1) { W = Wh + DD;     bi = bk; Y = Yk; sc = 1.0f; }
    else                      { W = Wh + 2 * DD; bi = bv; Y = Yv; sc = 1.0f; }
    gemm_h_body(X, W, bi, Y, 1, sc, gsm);
}

__global__ __launch_bounds__(256, 2) void gemm_out_h(
    const u16* __restrict__ X, const u16* __restrict__ Wh,
    const float* __restrict__ bo, float* __restrict__ Y)
{
    extern __shared__ u16 gsm[];
    gemm_h_body(X, Wh, bo, Y, 0, 1.0f, gsm);
}

// ---------------------------------------------------------------------------
// Attention fp16 v4: 128-row kv tiles, ex2.f16x2 exp, lsum via ones-column MMA,
// 3-stage cp.async ring with ONE barrier per tile.
// ---------------------------------------------------------------------------
#define KPH 72
#define KTILE 128
#define KBUFB (KTILE * 144)          // 18432 B per operand stage
#define OFF_VB (3 * KBUFB)           // V stages start after 3 K stages
#define ATT_SM (6 * KBUFB)           // 110592 B
#define NKT (S_ / KTILE)             // 16

__global__ __launch_bounds__(256, 2) void attn_h(
    const u16* __restrict__ Q, const u16* __restrict__ K,
    const u16* __restrict__ V, const float* __restrict__ wmix,
    u16* __restrict__ C)
{
    extern __shared__ u16 sm[];
    const unsigned sbase = smem_u32(sm);

    const int tid = threadIdx.x;
    const int lane = tid & 31, w = tid >> 5;
    const int g = lane >> 2, tig = lane & 3;
    const int s0 = blockIdx.x * 128;
    const int h = blockIdx.y;
    const int b = blockIdx.z;
    const size_t base = (size_t)b * S_ * D_ + (size_t)h * DH_;

    const u16* kgb = K + base;
    const u16* vgb = V + base;

    const int lrow = tid >> 3;       // 0..31
    const int lseg = tid & 7;

#define ATT_LOAD(kt_) do {                                                      \
        int st_ = (kt_) % 3;                                                    \
        unsigned sk_ = sbase + st_ * KBUFB;                                     \
        unsigned sv_ = sbase + OFF_VB + st_ * KBUFB;                            \
        const u16* kg_ = kgb + (size_t)(kt_) * KTILE * D_;                      \
        const u16* vg_ = vgb + (size_t)(kt_) * KTILE * D_;                      \
        _Pragma("unroll")                                                       \
        for (int u_ = 0; u_ < 4; u_++) {                                        \
            int row_ = lrow + u_ * 32;                                          \
            cp16(sk_ + row_ * 144 + lseg * 16, kg_ + (size_t)row_ * D_ + lseg * 8); \
            cp16(sv_ + row_ * 144 + lseg * 16, vg_ + (size_t)row_ * D_ + lseg * 8); \
        }                                                                       \
        CP_COMMIT();                                                            \
    } while (0)

    ATT_LOAD(0);
    ATT_LOAD(1);

    // Persistent Q fragments (Q pre-scaled by 0.125*log2e)
    u32 qA[4][4];
    {
        const u16* qp = Q + base + (size_t)(s0 + w * 16 + g) * D_;
        const u16* qp8 = qp + 8 * D_;
#pragma unroll
        for (int ks = 0; ks < 4; ks++) {
            qA[ks][0] = *(const u32*)(qp + ks * 16 + 2 * tig);
            qA[ks][1] = *(const u32*)(qp8 + ks * 16 + 2 * tig);
            qA[ks][2] = *(const u32*)(qp + ks * 16 + 8 + 2 * tig);
            qA[ks][3] = *(const u32*)(qp8 + ks * 16 + 8 + 2 * tig);
        }
    }

    float e0 = __expf(wmix[0]), e1 = __expf(wmix[1]);
    float inv = 1.0f / (e0 + e1);
    const float mix0 = e0 * inv;
    const float mix1l = e1 * inv * LN2SQ;

    float os[8][4] = {};
    float orl[8][4] = {};
    float ls[4] = {};                       // row sums via ones-column MMA
    const u32 oneb = (g == 0) ? 0x3C003C00u : 0u;

    const unsigned k_lrow = (lane & 7) * 144 + (lane >> 3) * 16;
    const unsigned v_lrow = (lane & 15) * 144 + (lane >> 4) * 16;

    for (int kt = 0; kt < NKT; kt++) {
        if (kt < NKT - 2) { CP_WAIT(1); } else { CP_WAIT(0); }
        __syncthreads();
        if (kt + 2 < NKT) ATT_LOAD(kt + 2);

        const unsigned skb = sbase + (kt % 3) * KBUFB;
        const unsigned svb = sbase + OFF_VB + (kt % 3) * KBUFB;

#pragma unroll
        for (int kvg = 0; kvg < 8; kvg++) {
            // --- QK via ldmatrix.x4 K-fragments ---
            float sce[4] = {0.f, 0.f, 0.f, 0.f};
            float sco[4] = {0.f, 0.f, 0.f, 0.f};
            const unsigned kbb = skb + (kvg * 16) * 144 + k_lrow;
#pragma unroll
            for (int ksp = 0; ksp < 2; ksp++) {
                u32 be0, be1, be2, be3, bo0, bo1, bo2, bo3;
                ldsm4(be0, be1, be2, be3, kbb + ksp * 64);
                ldsm4(bo0, bo1, bo2, bo3, kbb + 8 * 144 + ksp * 64);
                const int ks = 2 * ksp;
                mma16(sce, qA[ks][0], qA[ks][1], qA[ks][2], qA[ks][3], be0, be1);
                mma16(sce, qA[ks + 1][0], qA[ks + 1][1], qA[ks + 1][2], qA[ks + 1][3], be2, be3);
                mma16(sco, qA[ks][0], qA[ks][1], qA[ks][2], qA[ks][3], bo0, bo1);
                mma16(sco, qA[ks + 1][0], qA[ks + 1][1], qA[ks + 1][2], qA[ks + 1][3], bo2, bo3);
            }

            // --- pe = ex2(s') packed; pq = max(s',0)^2 packed ---
            u32 ape0 = ex2h2(h2pack(sce[0], sce[1]));
            u32 ape1 = ex2h2(h2pack(sce[2], sce[3]));
            u32 ape2 = ex2h2(h2pack(sco[0], sco[1]));
            u32 ape3 = ex2h2(h2pack(sco[2], sco[3]));

            float re0 = fmaxf(sce[0], 0.f), re1 = fmaxf(sce[1], 0.f);
            float re2 = fmaxf(sce[2], 0.f), re3 = fmaxf(sce[3], 0.f);
            float ro0 = fmaxf(sco[0], 0.f), ro1 = fmaxf(sco[1], 0.f);
            float ro2 = fmaxf(sco[2], 0.f), ro3 = fmaxf(sco[3], 0.f);
            u32 apq0 = h2pack(re0 * re0, re1 * re1);
            u32 apq1 = h2pack(re2 * re2, re3 * re3);
            u32 apq2 = h2pack(ro0 * ro0, ro1 * ro1);
            u32 apq3 = h2pack(ro2 * ro2, ro3 * ro3);

            // --- row sums of pe (tensor pipe; col 0 only) ---
            mma16(ls, ape0, ape1, ape2, ape3, oneb, oneb);

            // --- PV via ldmatrix.x4.trans V-fragments ---
            const unsigned vbb = svb + (kvg * 16) * 144 + v_lrow;
#pragma unroll
            for (int dtp = 0; dtp < 4; dtp++) {
                u32 v0, v1, v2, v3;
                ldsm4t(v0, v1, v2, v3, vbb + dtp * 32);
                mma16(os[2 * dtp], ape0, ape1, ape2, ape3, v0, v1);
                mma16(orl[2 * dtp], apq0, apq1, apq2, apq3, v0, v1);
                mma16(os[2 * dtp + 1], ape0, ape1, ape2, ape3, v2, v3);
                mma16(orl[2 * dtp + 1], apq0, apq1, apq2, apq3, v2, v3);
            }
        }
    }

    // Row sums live in col 0 (tig==0 lanes); broadcast within each quad.
    float l0 = __shfl_sync(0xffffffffu, ls[0], lane & 28);
    float l1 = __shfl_sync(0xffffffffu, ls[2], lane & 28);
    float f0 = mix0 / l0;
    float f1 = mix0 / l1;

    u16* crow = C + base + (size_t)(s0 + w * 16 + g) * D_;
    u16* crow8 = crow + 8 * D_;
#pragma unroll
    for (int dt = 0; dt < 8; dt++) {
        *(u32*)&crow[dt * 8 + 2 * tig] =
            h2pack(os[dt][0] * f0 + orl[dt][0] * mix1l,
                   os[dt][1] * f0 + orl[dt][1] * mix1l);
        *(u32*)&crow8[dt * 8 + 2 * tig] =
            h2pack(os[dt][2] * f1 + orl[dt][2] * mix1l,
                   os[dt][3] * f1 + orl[dt][3] * mix1l);
    }
#undef ATT_LOAD
}

// ---------------------------------------------------------------------------
extern "C" void kernel_launch(void* const* d_in, const int* in_sizes, int n_in,
                              void* d_out, int out_size)
{
    const float* hs   = (const float*)d_in[0];
    const float* Wq   = (const float*)d_in[1];
    const float* bq   = (const float*)d_in[2];
    const float* Wk   = (const float*)d_in[3];
    const float* bk   = (const float*)d_in[4];
    const float* Wv   = (const float*)d_in[5];
    const float* bv   = (const float*)d_in[6];
    const float* Wo   = (const float*)d_in[7];
    const float* bo   = (const float*)d_in[8];
    const float* wmix = (const float*)d_in[9];
    float* out = (float*)d_out;

    u16 *q, *k, *v, *c, *x, *wbuf;
    cudaGetSymbolAddress((void**)&q, g_Q);
    cudaGetSymbolAddress((void**)&k, g_K);
    cudaGetSymbolAddress((void**)&v, g_V);
    cudaGetSymbolAddress((void**)&c, g_C);
    cudaGetSymbolAddress((void**)&x, g_X);
    cudaGetSymbolAddress((void**)&wbuf, g_W);

    to_half_pre<<<2048, 256>>>(hs, Wq, Wk, Wv, Wo, x, wbuf);

    cudaFuncSetAttribute(gemm_qkv_h, cudaFuncAttributeMaxDynamicSharedMemorySize, GEMM_SM);
    gemm_qkv_h<<<dim3(D_ / 128, M_TOT / 128, 3), 256, GEMM_SM>>>(
        x, wbuf, bq, bk, bv, q, k, v);

    cudaFuncSetAttribute(attn_h, cudaFuncAttributeMaxDynamicSharedMemorySize, ATT_SM);
    attn_h<<<dim3(S_ / 128, H_, B_), 256, ATT_SM>>>(q, k, v, wmix, c);

    cudaFuncSetAttribute(gemm_out_h, cudaFuncAttributeMaxDynamicSharedMemorySize, GEMM_SM);
    gemm_out_h<<<dim3(D_ / 128, M_TOT / 128), 256, GEMM_SM>>>(
        c, wbuf + 3 * (size_t)DD, bo, out);
}